// round 5
// baseline (speedup 1.0000x reference)
#include <cuda_runtime.h>
#include <cuda_bf16.h>
#include <math_constants.h>

// Problem constants (shapes fixed by the dataset; runtime sizes are checked
// against these capacities via in_sizes).
#define NN 100000
#define EE 1600000
// layer dims
//  layer1: in 64 -> H=4, C=16 (concat -> 64)
//  layer2: in 64 -> H=4, C=64 (mean  -> 64)

// ---------------- device scratch (no allocation allowed) ----------------
__device__ float g_xl1[NN * 64];
__device__ float g_xr1[NN * 64];
__device__ float g_h1 [NN * 64];
__device__ float g_xl2[NN * 256];
__device__ float g_xr2[NN * 256];
__device__ int   g_counts[NN];
__device__ int   g_rowptr[NN + 1];
__device__ int   g_wofs[NN];
__device__ int   g_csr[EE];
__device__ int   g_bsum[128];
__device__ int   g_boff[128];
__device__ int   g_is64;

// ---------------- edge-index dtype detection (int64 vs int32) ----------------
// If the buffer is int64, node ids < 1e5 => every odd 32-bit word is zero.
// If int32, odd words are node ids, virtually surely nonzero somewhere.
__global__ void k_detect(const void* ei, long long e2 /* total 32/64-bit elems*2E */) {
    __shared__ int any;
    if (threadIdx.x == 0) any = 0;
    __syncthreads();
    const unsigned* p = (const unsigned*)ei;
    long long limit = 8192;
    if (limit > 2 * e2) limit = 2 * e2;  // int64 view occupies 2*e2 32-bit words at most
    for (long long i = 2 * (long long)threadIdx.x + 1; i < limit; i += 2 * blockDim.x)
        if (p[i] != 0u) any = 1;
    __syncthreads();
    if (threadIdx.x == 0) g_is64 = (any == 0) ? 1 : 0;
}

__device__ __forceinline__ int load_idx(const void* p, int is64, long long idx) {
    if (is64) return (int)(((const long long*)p)[idx]);
    return ((const int*)p)[idx];
}

// ---------------- CSR build ----------------
__global__ void k_zero(int n) {
    int i = blockIdx.x * blockDim.x + threadIdx.x;
    if (i < n) g_counts[i] = 0;
}

__global__ void k_hist(const void* ei, int E) {
    int e = blockIdx.x * blockDim.x + threadIdx.x;
    if (e >= E) return;
    int is64 = g_is64;
    int d = load_idx(ei, is64, (long long)E + e);
    atomicAdd(&g_counts[d], 1);
}

__global__ void k_scan_reduce(int N) {
    __shared__ int s[1024];
    int i = blockIdx.x * 1024 + threadIdx.x;
    int v = (i < N) ? g_counts[i] : 0;
    s[threadIdx.x] = v;
    __syncthreads();
    for (int off = 512; off > 0; off >>= 1) {
        if (threadIdx.x < off) s[threadIdx.x] += s[threadIdx.x + off];
        __syncthreads();
    }
    if (threadIdx.x == 0) g_bsum[blockIdx.x] = s[0];
}

__global__ void k_scan_top(int nb) {
    __shared__ int s[128];
    int tid = threadIdx.x;
    int v = (tid < nb) ? g_bsum[tid] : 0;
    s[tid] = v;
    __syncthreads();
    for (int off = 1; off < 128; off <<= 1) {
        int t = (tid >= off) ? s[tid - off] : 0;
        __syncthreads();
        s[tid] += t;
        __syncthreads();
    }
    if (tid < nb) g_boff[tid] = s[tid] - v;  // exclusive
}

__global__ void k_scan_apply(int N, int E) {
    __shared__ int s[1024];
    int tid = threadIdx.x;
    int i = blockIdx.x * 1024 + tid;
    int v = (i < N) ? g_counts[i] : 0;
    s[tid] = v;
    __syncthreads();
    for (int off = 1; off < 1024; off <<= 1) {
        int t = (tid >= off) ? s[tid - off] : 0;
        __syncthreads();
        s[tid] += t;
        __syncthreads();
    }
    int excl = s[tid] - v + g_boff[blockIdx.x];
    if (i < N) {
        g_rowptr[i] = excl;
        g_wofs[i] = excl;
    }
    if (i == N - 1) g_rowptr[N] = excl + v;  // == E
}

__global__ void k_scatter(const void* ei, int E) {
    int e = blockIdx.x * blockDim.x + threadIdx.x;
    if (e >= E) return;
    int is64 = g_is64;
    int d = load_idx(ei, is64, (long long)E + e);
    int s = load_idx(ei, is64, (long long)e);
    int pos = atomicAdd(&g_wofs[d], 1);
    g_csr[pos] = s;
}

// ---------------- GEMM 1: x[N,64] @ (Wl1|Wr1)[64,128] -> xl1,xr1 ----------------
__global__ __launch_bounds__(128) void k_gemm1(
    const float* __restrict__ x,
    const float* __restrict__ Wl, const float* __restrict__ bl,
    const float* __restrict__ Wr, const float* __restrict__ br, int N) {
    __shared__ float sW[64 * 128];
    __shared__ float sB[128];
    __shared__ float sX[32 * 64];
    int tid = threadIdx.x;
    for (int idx = tid; idx < 64 * 128; idx += 128) {
        int k = idx >> 7, j = idx & 127;
        sW[idx] = (j < 64) ? Wl[k * 64 + j] : Wr[k * 64 + (j - 64)];
    }
    sB[tid] = (tid < 64) ? bl[tid] : br[tid - 64];
    int row0 = blockIdx.x * 32;
    for (int idx = tid; idx < 32 * 64; idx += 128) {
        int r = idx >> 6, c = idx & 63;
        int gr = row0 + r;
        sX[idx] = (gr < N) ? x[(long long)gr * 64 + c] : 0.f;
    }
    __syncthreads();
    int cr = tid & 31, rr = tid >> 5;
    float acc[8][4];
#pragma unroll
    for (int i2 = 0; i2 < 8; i2++)
#pragma unroll
        for (int c = 0; c < 4; c++) acc[i2][c] = 0.f;
#pragma unroll 4
    for (int k = 0; k < 64; k++) {
        float w0 = sW[k * 128 + cr];
        float w1 = sW[k * 128 + cr + 32];
        float w2 = sW[k * 128 + cr + 64];
        float w3 = sW[k * 128 + cr + 96];
#pragma unroll
        for (int i2 = 0; i2 < 8; i2++) {
            float xv = sX[(rr * 8 + i2) * 64 + k];
            acc[i2][0] += xv * w0;
            acc[i2][1] += xv * w1;
            acc[i2][2] += xv * w2;
            acc[i2][3] += xv * w3;
        }
    }
#pragma unroll
    for (int i2 = 0; i2 < 8; i2++) {
        int gr = row0 + rr * 8 + i2;
        if (gr >= N) continue;
#pragma unroll
        for (int c = 0; c < 4; c++) {
            int j = cr + 32 * c;
            float v = acc[i2][c] + sB[j];
            if (j < 64) g_xl1[(long long)gr * 64 + j] = v;
            else        g_xr1[(long long)gr * 64 + (j - 64)] = v;
        }
    }
}

// ---------------- GEMM 2: h1[N,64] @ (Wl2|Wr2)[64,512] -> xl2,xr2 ----------------
__global__ __launch_bounds__(128) void k_gemm2(
    const float* __restrict__ Wl, const float* __restrict__ bl,
    const float* __restrict__ Wr, const float* __restrict__ br, int N) {
    __shared__ float sW[64 * 128];
    __shared__ float sB[128];
    __shared__ float sX[32 * 64];
    int tid = threadIdx.x;
    int colbase = blockIdx.y * 128;  // 0..511 in steps of 128
    for (int idx = tid; idx < 64 * 128; idx += 128) {
        int k = idx >> 7, jj = idx & 127;
        int cg = colbase + jj;
        sW[idx] = (cg < 256) ? Wl[k * 256 + cg] : Wr[k * 256 + (cg - 256)];
    }
    {
        int cg = colbase + tid;
        sB[tid] = (cg < 256) ? bl[cg] : br[cg - 256];
    }
    int row0 = blockIdx.x * 32;
    for (int idx = tid; idx < 32 * 64; idx += 128) {
        int r = idx >> 6, c = idx & 63;
        int gr = row0 + r;
        sX[idx] = (gr < N) ? g_h1[(long long)gr * 64 + c] : 0.f;
    }
    __syncthreads();
    int cr = tid & 31, rr = tid >> 5;
    float acc[8][4];
#pragma unroll
    for (int i2 = 0; i2 < 8; i2++)
#pragma unroll
        for (int c = 0; c < 4; c++) acc[i2][c] = 0.f;
#pragma unroll 4
    for (int k = 0; k < 64; k++) {
        float w0 = sW[k * 128 + cr];
        float w1 = sW[k * 128 + cr + 32];
        float w2 = sW[k * 128 + cr + 64];
        float w3 = sW[k * 128 + cr + 96];
#pragma unroll
        for (int i2 = 0; i2 < 8; i2++) {
            float xv = sX[(rr * 8 + i2) * 64 + k];
            acc[i2][0] += xv * w0;
            acc[i2][1] += xv * w1;
            acc[i2][2] += xv * w2;
            acc[i2][3] += xv * w3;
        }
    }
#pragma unroll
    for (int i2 = 0; i2 < 8; i2++) {
        int gr = row0 + rr * 8 + i2;
        if (gr >= N) continue;
#pragma unroll
        for (int c = 0; c < 4; c++) {
            int j = cr + 32 * c;
            int cg = colbase + j;
            float v = acc[i2][c] + sB[j];
            if (cg < 256) g_xl2[(long long)gr * 256 + cg] = v;
            else          g_xr2[(long long)gr * 256 + (cg - 256)] = v;
        }
    }
}

// ---------------- Layer 1 edge kernel: warp per dst node, online softmax ----------------
// Layout: 64 values [H=4,C=16]; lane holds v=lane (k0) and v=lane+32 (k1).
// head(v) = v>>4: k0 -> heads {0,1} (lane<16 ? 0 : 1), k1 -> heads {2,3}.
__global__ __launch_bounds__(256) void k_l1edge(
    const float* __restrict__ att, const float* __restrict__ bo, int N) {
    int warp = (blockIdx.x * blockDim.x + threadIdx.x) >> 5;
    int lane = threadIdx.x & 31;
    if (warp >= N) return;
    int i = warp;
    float xr0 = g_xr1[(long long)i * 64 + lane];
    float xr1v = g_xr1[(long long)i * 64 + lane + 32];
    float a0 = att[lane], a1 = att[lane + 32];
    float m[4], d[4];
#pragma unroll
    for (int h = 0; h < 4; h++) { m[h] = -1e30f; d[h] = 0.f; }
    float acc0 = 0.f, acc1 = 0.f;
    int beg = g_rowptr[i], end = g_rowptr[i + 1];
    int hsel = lane >> 4;  // 0 or 1
    for (int j = beg - 1; j < end; j++) {
        int s = (j < beg) ? i : g_csr[j];  // self-loop first
        float xl0 = __ldg(&g_xl1[(long long)s * 64 + lane]);
        float xl1v = __ldg(&g_xl1[(long long)s * 64 + lane + 32]);
        float t0 = xl0 + xr0;  t0 = (t0 > 0.f) ? t0 : 0.2f * t0;
        float t1 = xl1v + xr1v; t1 = (t1 > 0.f) ? t1 : 0.2f * t1;
        float p0 = a0 * t0;
        float p1 = a1 * t1;
        // sum within 16-lane halves
#pragma unroll
        for (int off = 8; off >= 1; off >>= 1) {
            p0 += __shfl_xor_sync(0xFFFFFFFFu, p0, off);
            p1 += __shfl_xor_sync(0xFFFFFFFFu, p1, off);
        }
        float sc[4];
        sc[0] = __shfl_sync(0xFFFFFFFFu, p0, 0);
        sc[1] = __shfl_sync(0xFFFFFFFFu, p0, 16);
        sc[2] = __shfl_sync(0xFFFFFFFFu, p1, 0);
        sc[3] = __shfl_sync(0xFFFFFFFFu, p1, 16);
        float scale[4], w[4];
#pragma unroll
        for (int h = 0; h < 4; h++) {
            float nm = fmaxf(m[h], sc[h]);
            scale[h] = __expf(m[h] - nm);
            w[h] = __expf(sc[h] - nm);
            d[h] = d[h] * scale[h] + w[h];
            m[h] = nm;
        }
        acc0 = acc0 * scale[hsel]     + w[hsel]     * xl0;
        acc1 = acc1 * scale[hsel + 2] + w[hsel + 2] * xl1v;
    }
    float o0 = acc0 / (d[hsel] + 1e-16f) + bo[lane];
    float o1 = acc1 / (d[hsel + 2] + 1e-16f) + bo[lane + 32];
    g_h1[(long long)i * 64 + lane]      = fmaxf(o0, 0.f);
    g_h1[(long long)i * 64 + lane + 32] = fmaxf(o1, 0.f);
}

// ---------------- Layer 2 edge kernel: warp per dst node ----------------
// 256 values [H=4,C=64]; lane holds v = lane + 32k, k=0..7; head(v) = k>>1;
// out col c = lane + 32*(k&1); mean over heads.
__global__ __launch_bounds__(256) void k_l2edge(
    const float* __restrict__ att, const float* __restrict__ bo,
    float* __restrict__ out, int N) {
    int warp = (blockIdx.x * blockDim.x + threadIdx.x) >> 5;
    int lane = threadIdx.x & 31;
    if (warp >= N) return;
    int i = warp;
    float xr[8], av[8];
#pragma unroll
    for (int k = 0; k < 8; k++) {
        xr[k] = g_xr2[(long long)i * 256 + lane + 32 * k];
        av[k] = att[lane + 32 * k];
    }
    float m[4], d[4], acc[8];
#pragma unroll
    for (int h = 0; h < 4; h++) { m[h] = -1e30f; d[h] = 0.f; }
#pragma unroll
    for (int k = 0; k < 8; k++) acc[k] = 0.f;
    int beg = g_rowptr[i], end = g_rowptr[i + 1];
    for (int j = beg - 1; j < end; j++) {
        int s = (j < beg) ? i : g_csr[j];  // self-loop first
        const float* xlp = &g_xl2[(long long)s * 256 + lane];
        float xl[8];
#pragma unroll
        for (int k = 0; k < 8; k++) xl[k] = __ldg(xlp + 32 * k);
        float ph[4];
#pragma unroll
        for (int h = 0; h < 4; h++) {
            float t0 = xl[2 * h] + xr[2 * h];
            t0 = (t0 > 0.f) ? t0 : 0.2f * t0;
            float t1 = xl[2 * h + 1] + xr[2 * h + 1];
            t1 = (t1 > 0.f) ? t1 : 0.2f * t1;
            ph[h] = av[2 * h] * t0 + av[2 * h + 1] * t1;
        }
#pragma unroll
        for (int off = 16; off >= 1; off >>= 1) {
#pragma unroll
            for (int h = 0; h < 4; h++)
                ph[h] += __shfl_xor_sync(0xFFFFFFFFu, ph[h], off);
        }
        float scale[4], w[4];
#pragma unroll
        for (int h = 0; h < 4; h++) {
            float nm = fmaxf(m[h], ph[h]);
            scale[h] = __expf(m[h] - nm);
            w[h] = __expf(ph[h] - nm);
            d[h] = d[h] * scale[h] + w[h];
            m[h] = nm;
        }
#pragma unroll
        for (int k = 0; k < 8; k++) {
            int h = k >> 1;
            acc[k] = acc[k] * scale[h] + w[h] * xl[k];
        }
    }
    float oA = 0.f, oB = 0.f;
#pragma unroll
    for (int h = 0; h < 4; h++) {
        float inv = 1.0f / (d[h] + 1e-16f);
        oA += acc[2 * h] * inv;
        oB += acc[2 * h + 1] * inv;
    }
    oA = 0.25f * oA + bo[lane];
    oB = 0.25f * oB + bo[lane + 32];
    out[(long long)i * 64 + lane]      = fmaxf(oA, 0.f);
    out[(long long)i * 64 + lane + 32] = fmaxf(oB, 0.f);
}

// ---------------- launch ----------------
extern "C" void kernel_launch(void* const* d_in, const int* in_sizes, int n_in,
                              void* d_out, int out_size) {
    const float* x   = (const float*)d_in[0];
    const void*  ei  = d_in[1];
    // d_in[2] = frame_mask (unused by the reference)
    const float* Wl1 = (const float*)d_in[3];
    const float* bl1 = (const float*)d_in[4];
    const float* Wr1 = (const float*)d_in[5];
    const float* br1 = (const float*)d_in[6];
    const float* att1 = (const float*)d_in[7];
    const float* bo1 = (const float*)d_in[8];
    const float* Wl2 = (const float*)d_in[9];
    const float* bl2 = (const float*)d_in[10];
    const float* Wr2 = (const float*)d_in[11];
    const float* br2 = (const float*)d_in[12];
    const float* att2 = (const float*)d_in[13];
    const float* bo2 = (const float*)d_in[14];

    int N = in_sizes[0] / 64;
    int E = in_sizes[1] / 2;
    if (N > NN) N = NN;
    if (E > EE) E = EE;

    // edge-index dtype sniffing (int64 vs int32) — fully device-side
    k_detect<<<1, 256>>>(ei, (long long)E * 2);

    // CSR build
    int nb = (N + 1023) / 1024;
    k_zero<<<nb, 1024>>>(N);
    k_hist<<<(E + 255) / 256, 256>>>(ei, E);
    k_scan_reduce<<<nb, 1024>>>(N);
    k_scan_top<<<1, 128>>>(nb);
    k_scan_apply<<<nb, 1024>>>(N, E);
    k_scatter<<<(E + 255) / 256, 256>>>(ei, E);

    // layer 1
    int rb = (N + 31) / 32;
    k_gemm1<<<rb, 128>>>(x, Wl1, bl1, Wr1, br1, N);
    k_l1edge<<<(N + 7) / 8, 256>>>(att1, bo1, N);

    // layer 2
    dim3 g2(rb, 4);
    k_gemm2<<<g2, 128>>>(Wl2, bl2, Wr2, br2, N);
    k_l2edge<<<(N + 7) / 8, 256>>>(att2, bo2, (float*)d_out, N);
}

// round 11
// speedup vs baseline: 1.2079x; 1.2079x over previous
#include <cuda_runtime.h>
#include <cuda_fp16.h>
#include <math_constants.h>

#define NN 100000
#define EE 1600000

// ---------------- device scratch (no allocation allowed) ----------------
__device__ __align__(16) float  g_xl1[NN * 64];
__device__ __align__(16) float  g_xr1[NN * 64];
__device__ __align__(16) float  g_h1 [NN * 64];
__device__ __align__(16) __half g_xl2h[NN * 256];   // fp16 gather table (51.2MB, L2-resident)
__device__ __align__(16) float  g_xr2[NN * 256];
__device__ int   g_counts[NN];
__device__ int   g_rowptr[NN + 1];
__device__ int   g_wofs[NN];
__device__ int   g_csr[EE];
__device__ int   g_bsum[128];
__device__ int   g_boff[128];
__device__ int   g_is64;

// ---------------- f32x2 packed helpers ----------------
__device__ __forceinline__ unsigned long long pk2(float a, float b) {
    unsigned long long r;
    asm("mov.b64 %0, {%1, %2};" : "=l"(r) : "f"(a), "f"(b));
    return r;
}
__device__ __forceinline__ unsigned long long fma2(unsigned long long a,
                                                   unsigned long long b,
                                                   unsigned long long c) {
    unsigned long long d;
    asm("fma.rn.f32x2 %0, %1, %2, %3;" : "=l"(d) : "l"(a), "l"(b), "l"(c));
    return d;
}
__device__ __forceinline__ float2 unpk(unsigned long long v) {
    float2 f;
    asm("mov.b64 {%0, %1}, %2;" : "=f"(f.x), "=f"(f.y) : "l"(v));
    return f;
}

// ---------------- edge-index dtype detection (int64 vs int32) ----------------
__global__ void k_detect(const void* ei, long long e2) {
    __shared__ int any;
    if (threadIdx.x == 0) any = 0;
    __syncthreads();
    const unsigned* p = (const unsigned*)ei;
    long long limit = 8192;
    if (limit > 2 * e2) limit = 2 * e2;
    for (long long i = 2 * (long long)threadIdx.x + 1; i < limit; i += 2 * blockDim.x)
        if (p[i] != 0u) any = 1;
    __syncthreads();
    if (threadIdx.x == 0) g_is64 = (any == 0) ? 1 : 0;
}

__device__ __forceinline__ int load_idx(const void* p, int is64, long long idx) {
    if (is64) return (int)(((const long long*)p)[idx]);
    return ((const int*)p)[idx];
}

// ---------------- CSR build ----------------
__global__ void k_zero(int n) {
    int i = blockIdx.x * blockDim.x + threadIdx.x;
    if (i < n) g_counts[i] = 0;
}

__global__ void k_hist(const void* ei, int E) {
    int e = blockIdx.x * blockDim.x + threadIdx.x;
    if (e >= E) return;
    int is64 = g_is64;
    int d = load_idx(ei, is64, (long long)E + e);
    atomicAdd(&g_counts[d], 1);
}

__global__ void k_scan_reduce(int N) {
    __shared__ int s[1024];
    int i = blockIdx.x * 1024 + threadIdx.x;
    int v = (i < N) ? g_counts[i] : 0;
    s[threadIdx.x] = v;
    __syncthreads();
    for (int off = 512; off > 0; off >>= 1) {
        if (threadIdx.x < off) s[threadIdx.x] += s[threadIdx.x + off];
        __syncthreads();
    }
    if (threadIdx.x == 0) g_bsum[blockIdx.x] = s[0];
}

__global__ void k_scan_top(int nb) {
    __shared__ int s[128];
    int tid = threadIdx.x;
    int v = (tid < nb) ? g_bsum[tid] : 0;
    s[tid] = v;
    __syncthreads();
    for (int off = 1; off < 128; off <<= 1) {
        int t = (tid >= off) ? s[tid - off] : 0;
        __syncthreads();
        s[tid] += t;
        __syncthreads();
    }
    if (tid < nb) g_boff[tid] = s[tid] - v;  // exclusive
}

__global__ void k_scan_apply(int N, int E) {
    __shared__ int s[1024];
    int tid = threadIdx.x;
    int i = blockIdx.x * 1024 + tid;
    int v = (i < N) ? g_counts[i] : 0;
    s[tid] = v;
    __syncthreads();
    for (int off = 1; off < 1024; off <<= 1) {
        int t = (tid >= off) ? s[tid - off] : 0;
        __syncthreads();
        s[tid] += t;
        __syncthreads();
    }
    int excl = s[tid] - v + g_boff[blockIdx.x];
    if (i < N) {
        g_rowptr[i] = excl;
        g_wofs[i] = excl;
    }
    if (i == N - 1) g_rowptr[N] = excl + v;
}

__global__ void k_scatter(const void* ei, int E) {
    int e = blockIdx.x * blockDim.x + threadIdx.x;
    if (e >= E) return;
    int is64 = g_is64;
    int d = load_idx(ei, is64, (long long)E + e);
    int s = load_idx(ei, is64, (long long)e);
    int pos = atomicAdd(&g_wofs[d], 1);
    g_csr[pos] = s;
}

// ---------------- GEMM 1: x[N,64] @ (Wl1|Wr1)[64,128] -> xl1,xr1 (fp32) ------
// 64 rows/block, 256 threads, f32x2 packed accumulation over row-pairs.
// sXT is the transposed X tile with an XOR swizzle (keeps float2 pairs adjacent,
// avoids the 32-way transpose-write conflict without padding; 48KB static smem).
__global__ __launch_bounds__(256) void k_gemm1(
    const float* __restrict__ x,
    const float* __restrict__ Wl, const float* __restrict__ bl,
    const float* __restrict__ Wr, const float* __restrict__ br, int N) {
    __shared__ float sW[64 * 128];      // 32KB
    __shared__ float sXT[64 * 64];      // 16KB, sXT[k][r ^ (k&30)]
    int tid = threadIdx.x;
    for (int idx = tid; idx < 64 * 128; idx += 256) {
        int k = idx >> 7, j = idx & 127;
        sW[idx] = (j < 64) ? Wl[k * 64 + j] : Wr[k * 64 + (j - 64)];
    }
    int row0 = blockIdx.x * 64;
    for (int idx = tid; idx < 64 * 64; idx += 256) {
        int r = idx >> 6, c = idx & 63;
        int gr = row0 + r;
        sXT[c * 64 + (r ^ (c & 30))] = (gr < N) ? x[(long long)gr * 64 + c] : 0.f;
    }
    __syncthreads();
    int cr = tid & 31, rr = tid >> 5;       // rr 0..7 -> rows rr*8..rr*8+7
    unsigned long long acc2[4][4];
#pragma unroll
    for (int p = 0; p < 4; p++)
#pragma unroll
        for (int c = 0; c < 4; c++) acc2[p][c] = 0ull;
#pragma unroll 4
    for (int k = 0; k < 64; k++) {
        unsigned long long wp[4];
#pragma unroll
        for (int c = 0; c < 4; c++) {
            float w = sW[k * 128 + cr + 32 * c];
            wp[c] = pk2(w, w);
        }
#pragma unroll
        for (int p = 0; p < 4; p++) {
            int r0 = rr * 8 + 2 * p;
            unsigned long long xv =
                *(const unsigned long long*)&sXT[k * 64 + (r0 ^ (k & 30))];
#pragma unroll
            for (int c = 0; c < 4; c++) acc2[p][c] = fma2(xv, wp[c], acc2[p][c]);
        }
    }
#pragma unroll
    for (int p = 0; p < 4; p++) {
        int r0 = row0 + rr * 8 + 2 * p;
#pragma unroll
        for (int c = 0; c < 4; c++) {
            int j = cr + 32 * c;
            float b = (j < 64) ? bl[j] : br[j - 64];
            float2 v = unpk(acc2[p][c]);
            if (r0 < N) {
                float vv = v.x + b;
                if (j < 64) g_xl1[r0 * 64 + j] = vv;
                else        g_xr1[r0 * 64 + (j - 64)] = vv;
            }
            if (r0 + 1 < N) {
                float vv = v.y + b;
                if (j < 64) g_xl1[(r0 + 1) * 64 + j] = vv;
                else        g_xr1[(r0 + 1) * 64 + (j - 64)] = vv;
            }
        }
    }
}

// ---------------- GEMM 2: h1[N,64] @ (Wl2|Wr2)[64,512] -> xl2(fp16), xr2(fp32)
__global__ __launch_bounds__(256) void k_gemm2(
    const float* __restrict__ Wl, const float* __restrict__ bl,
    const float* __restrict__ Wr, const float* __restrict__ br, int N) {
    __shared__ float sW[64 * 128];
    __shared__ float sXT[64 * 64];
    int tid = threadIdx.x;
    int colbase = blockIdx.y * 128;
    for (int idx = tid; idx < 64 * 128; idx += 256) {
        int k = idx >> 7, jj = idx & 127;
        int cg = colbase + jj;
        sW[idx] = (cg < 256) ? Wl[k * 256 + cg] : Wr[k * 256 + (cg - 256)];
    }
    int row0 = blockIdx.x * 64;
    for (int idx = tid; idx < 64 * 64; idx += 256) {
        int r = idx >> 6, c = idx & 63;
        int gr = row0 + r;
        sXT[c * 64 + (r ^ (c & 30))] = (gr < N) ? g_h1[gr * 64 + c] : 0.f;
    }
    __syncthreads();
    int cr = tid & 31, rr = tid >> 5;
    unsigned long long acc2[4][4];
#pragma unroll
    for (int p = 0; p < 4; p++)
#pragma unroll
        for (int c = 0; c < 4; c++) acc2[p][c] = 0ull;
#pragma unroll 4
    for (int k = 0; k < 64; k++) {
        unsigned long long wp[4];
#pragma unroll
        for (int c = 0; c < 4; c++) {
            float w = sW[k * 128 + cr + 32 * c];
            wp[c] = pk2(w, w);
        }
#pragma unroll
        for (int p = 0; p < 4; p++) {
            int r0 = rr * 8 + 2 * p;
            unsigned long long xv =
                *(const unsigned long long*)&sXT[k * 64 + (r0 ^ (k & 30))];
#pragma unroll
            for (int c = 0; c < 4; c++) acc2[p][c] = fma2(xv, wp[c], acc2[p][c]);
        }
    }
#pragma unroll
    for (int p = 0; p < 4; p++) {
        int r0 = row0 + rr * 8 + 2 * p;
#pragma unroll
        for (int c = 0; c < 4; c++) {
            int cg = colbase + cr + 32 * c;
            float b = (cg < 256) ? bl[cg] : br[cg - 256];
            float2 v = unpk(acc2[p][c]);
            if (r0 < N) {
                float vv = v.x + b;
                if (cg < 256) g_xl2h[r0 * 256 + cg] = __float2half_rn(vv);
                else          g_xr2[r0 * 256 + (cg - 256)] = vv;
            }
            if (r0 + 1 < N) {
                float vv = v.y + b;
                if (cg < 256) g_xl2h[(r0 + 1) * 256 + cg] = __float2half_rn(vv);
                else          g_xr2[(r0 + 1) * 256 + (cg - 256)] = vv;
            }
        }
    }
}

// ---------------- Layer 1 edge kernel ----------------
// Warp per dst node. Lane l owns elements {2l, 2l+1}; head h = l>>3 (C=16).
// Single LDG.64 per lane per edge; score reduce = 3 shuffles within 8-lane
// group; softmax base = self-loop score (no running-max rescale).
__global__ __launch_bounds__(256) void k_l1edge(
    const float* __restrict__ att, const float* __restrict__ bo, int N) {
    int warp = (blockIdx.x * blockDim.x + threadIdx.x) >> 5;
    int lane = threadIdx.x & 31;
    if (warp >= N) return;
    int i = warp;
    const int* __restrict__ csr = g_csr;
    float2 xr = *(const float2*)&g_xr1[i * 64 + 2 * lane];
    float2 a  = __ldg((const float2*)&att[2 * lane]);
    float d = 0.f, m0 = 0.f, acc0 = 0.f, acc1 = 0.f;
    int beg = __ldg(&g_rowptr[i]), end = __ldg(&g_rowptr[i + 1]);
    for (int j = beg - 1; j < end; j++) {
        int s = (j < beg) ? i : __ldg(&csr[j]);  // self-loop first
        float2 xl = __ldg((const float2*)&g_xl1[s * 64 + 2 * lane]);
        float t0 = xl.x + xr.x; t0 = fmaxf(t0, 0.2f * t0);
        float t1 = xl.y + xr.y; t1 = fmaxf(t1, 0.2f * t1);
        float p = fmaf(a.x, t0, a.y * t1);
        p += __shfl_xor_sync(0xFFFFFFFFu, p, 1);
        p += __shfl_xor_sync(0xFFFFFFFFu, p, 2);
        p += __shfl_xor_sync(0xFFFFFFFFu, p, 4);
        float w;
        if (j < beg) { m0 = p; w = 1.f; }
        else w = __expf(p - m0);
        d += w;
        acc0 = fmaf(w, xl.x, acc0);
        acc1 = fmaf(w, xl.y, acc1);
    }
    float inv = 1.f / d;  // d >= 1 (self term)
    float2 bov = __ldg((const float2*)&bo[2 * lane]);
    float2 o;
    o.x = fmaxf(fmaf(acc0, inv, bov.x), 0.f);
    o.y = fmaxf(fmaf(acc1, inv, bov.y), 0.f);
    *(float2*)&g_h1[i * 64 + 2 * lane] = o;
}

// ---------------- Layer 2 edge kernel ----------------
// Warp per dst node. Lane l owns elements {8l..8l+7}; head h = l>>3 (C=64).
// Single LDG.128 (8 fp16) per lane per edge; 3-shuffle score reduce;
// self-score softmax base; cross-head mean at the end via 2 shuffle levels.
__global__ __launch_bounds__(256) void k_l2edge(
    const float* __restrict__ att, const float* __restrict__ bo,
    float* __restrict__ out, int N) {
    int warp = (blockIdx.x * blockDim.x + threadIdx.x) >> 5;
    int lane = threadIdx.x & 31;
    if (warp >= N) return;
    int i = warp;
    const int* __restrict__ csr = g_csr;
    int h8 = lane * 8;
    float xr[8], av[8];
    {
        float4 r0 = *(const float4*)&g_xr2[i * 256 + h8];
        float4 r1 = *(const float4*)&g_xr2[i * 256 + h8 + 4];
        xr[0] = r0.x; xr[1] = r0.y; xr[2] = r0.z; xr[3] = r0.w;
        xr[4] = r1.x; xr[5] = r1.y; xr[6] = r1.z; xr[7] = r1.w;
        float4 a0 = __ldg((const float4*)&att[h8]);
        float4 a1 = __ldg((const float4*)&att[h8 + 4]);
        av[0] = a0.x; av[1] = a0.y; av[2] = a0.z; av[3] = a0.w;
        av[4] = a1.x; av[5] = a1.y; av[6] = a1.z; av[7] = a1.w;
    }
    float acc[8];
#pragma unroll
    for (int k = 0; k < 8; k++) acc[k] = 0.f;
    float d = 0.f, m0 = 0.f;
    int beg = __ldg(&g_rowptr[i]), end = __ldg(&g_rowptr[i + 1]);
    for (int j = beg - 1; j < end; j++) {
        int s = (j < beg) ? i : __ldg(&csr[j]);  // self-loop first
        uint4 raw = __ldg((const uint4*)&g_xl2h[s * 256 + h8]);
        float xl[8];
        {
            float2 f;
            f = __half22float2(*reinterpret_cast<__half2*>(&raw.x));
            xl[0] = f.x; xl[1] = f.y;
            f = __half22float2(*reinterpret_cast<__half2*>(&raw.y));
            xl[2] = f.x; xl[3] = f.y;
            f = __half22float2(*reinterpret_cast<__half2*>(&raw.z));
            xl[4] = f.x; xl[5] = f.y;
            f = __half22float2(*reinterpret_cast<__half2*>(&raw.w));
            xl[6] = f.x; xl[7] = f.y;
        }
        float p = 0.f;
#pragma unroll
        for (int k = 0; k < 8; k++) {
            float t = xl[k] + xr[k];
            t = fmaxf(t, 0.2f * t);          // leaky_relu, slope<1
            p = fmaf(av[k], t, p);
        }
        p += __shfl_xor_sync(0xFFFFFFFFu, p, 1);
        p += __shfl_xor_sync(0xFFFFFFFFu, p, 2);
        p += __shfl_xor_sync(0xFFFFFFFFu, p, 4);
        float w;
        if (j < beg) { m0 = p; w = 1.f; }
        else w = __expf(p - m0);
        d += w;
#pragma unroll
        for (int k = 0; k < 8; k++) acc[k] = fmaf(w, xl[k], acc[k]);
    }
    float inv = 1.f / d;
    float r[8];
#pragma unroll
    for (int k = 0; k < 8; k++) r[k] = acc[k] * inv;
    // mean over heads: sum lanes {l, l^8, l^16, l^24}
#pragma unroll
    for (int k = 0; k < 8; k++) r[k] += __shfl_xor_sync(0xFFFFFFFFu, r[k], 8);
#pragma unroll
    for (int k = 0; k < 8; k++) r[k] += __shfl_xor_sync(0xFFFFFFFFu, r[k], 16);
    if (lane < 8) {
        float4 b0 = __ldg((const float4*)&bo[h8]);
        float4 b1 = __ldg((const float4*)&bo[h8 + 4]);
        float4 o0, o1;
        o0.x = fmaxf(fmaf(0.25f, r[0], b0.x), 0.f);
        o0.y = fmaxf(fmaf(0.25f, r[1], b0.y), 0.f);
        o0.z = fmaxf(fmaf(0.25f, r[2], b0.z), 0.f);
        o0.w = fmaxf(fmaf(0.25f, r[3], b0.w), 0.f);
        o1.x = fmaxf(fmaf(0.25f, r[4], b1.x), 0.f);
        o1.y = fmaxf(fmaf(0.25f, r[5], b1.y), 0.f);
        o1.z = fmaxf(fmaf(0.25f, r[6], b1.z), 0.f);
        o1.w = fmaxf(fmaf(0.25f, r[7], b1.w), 0.f);
        *(float4*)&out[i * 64 + h8]     = o0;
        *(float4*)&out[i * 64 + h8 + 4] = o1;
    }
}

// ---------------- launch ----------------
extern "C" void kernel_launch(void* const* d_in, const int* in_sizes, int n_in,
                              void* d_out, int out_size) {
    const float* x   = (const float*)d_in[0];
    const void*  ei  = d_in[1];
    // d_in[2] = frame_mask (unused by the reference)
    const float* Wl1 = (const float*)d_in[3];
    const float* bl1 = (const float*)d_in[4];
    const float* Wr1 = (const float*)d_in[5];
    const float* br1 = (const float*)d_in[6];
    const float* att1 = (const float*)d_in[7];
    const float* bo1 = (const float*)d_in[8];
    const float* Wl2 = (const float*)d_in[9];
    const float* bl2 = (const float*)d_in[10];
    const float* Wr2 = (const float*)d_in[11];
    const float* br2 = (const float*)d_in[12];
    const float* att2 = (const float*)d_in[13];
    const float* bo2 = (const float*)d_in[14];

    int N = in_sizes[0] / 64;
    int E = in_sizes[1] / 2;
    if (N > NN) N = NN;
    if (E > EE) E = EE;

    // edge-index dtype sniffing (int64 vs int32) — fully device-side
    k_detect<<<1, 256>>>(ei, (long long)E * 2);

    // CSR build
    int nb = (N + 1023) / 1024;
    k_zero<<<nb, 1024>>>(N);
    k_hist<<<(E + 255) / 256, 256>>>(ei, E);
    k_scan_reduce<<<nb, 1024>>>(N);
    k_scan_top<<<1, 128>>>(nb);
    k_scan_apply<<<nb, 1024>>>(N, E);
    k_scatter<<<(E + 255) / 256, 256>>>(ei, E);

    // layer 1
    int rb = (N + 63) / 64;
    k_gemm1<<<rb, 256>>>(x, Wl1, bl1, Wr1, br1, N);
    k_l1edge<<<(N + 7) / 8, 256>>>(att1, bo1, N);

    // layer 2
    dim3 g2(rb, 4);
    k_gemm2<<<g2, 256>>>(Wl2, bl2, Wr2, br2, N);
    k_l2edge<<<(N + 7) / 8, 256>>>(att2, bo2, (float*)d_out, N);
}

// round 12
// speedup vs baseline: 1.8569x; 1.5373x over previous
#include <cuda_runtime.h>
#include <cuda_fp16.h>
#include <math_constants.h>

#define NN 100000
#define EE 1600000
#define NB 128
#define NT 1024

// ---------------- device scratch (no allocation allowed) ----------------
__device__ __align__(16) float  g_xl1[NN * 64];
__device__ __align__(16) float  g_xr1[NN * 64];
__device__ __align__(16) float  g_h1 [NN * 64];
__device__ __align__(16) __half g_xl2h[NN * 256];   // fp16 gather table (51.2MB)
__device__ __align__(16) float  g_xr2[NN * 256];
__device__ int      g_counts[NN];
__device__ int      g_rowptr[NN + 1];
__device__ int      g_wofs[NN];
__device__ int      g_csr[EE];
__device__ int      g_bsum[NB];
__device__ int      g_boff[NB];
__device__ int      g_is64;
__device__ unsigned g_barcnt;     // zero-init
__device__ unsigned g_barphase;   // monotonically increasing across replays

// ---------------- f32x2 packed helpers ----------------
__device__ __forceinline__ unsigned long long pk2(float a, float b) {
    unsigned long long r;
    asm("mov.b64 %0, {%1, %2};" : "=l"(r) : "f"(a), "f"(b));
    return r;
}
__device__ __forceinline__ unsigned long long fma2(unsigned long long a,
                                                   unsigned long long b,
                                                   unsigned long long c) {
    unsigned long long d;
    asm("fma.rn.f32x2 %0, %1, %2, %3;" : "=l"(d) : "l"(a), "l"(b), "l"(c));
    return d;
}
__device__ __forceinline__ float2 unpk(unsigned long long v) {
    float2 f;
    asm("mov.b64 {%0, %1}, %2;" : "=f"(f.x), "=f"(f.y) : "l"(v));
    return f;
}

__device__ __forceinline__ int load_idx(const void* p, int is64, long long idx) {
    if (is64) return (int)(((const long long*)p)[idx]);
    return ((const int*)p)[idx];
}

// ---------------- grid barrier (sense via monotonic phase counter) ----------
__device__ __forceinline__ void gridbar() {
    __syncthreads();
    if (threadIdx.x == 0) {
        __threadfence();
        unsigned ph = *(volatile unsigned*)&g_barphase;
        if (atomicAdd(&g_barcnt, 1u) == NB - 1u) {
            g_barcnt = 0u;
            __threadfence();
            *(volatile unsigned*)&g_barphase = ph + 1u;
        } else {
            while (*(volatile unsigned*)&g_barphase == ph) {}
        }
        __threadfence();
    }
    __syncthreads();
}

// ---------------- fused: detect + zero + gemm1 | hist | scan | scatter -------
// 128 blocks x 1024 threads, all co-resident (1 block/SM on 148+ SMs).
__global__ __launch_bounds__(NT, 1) void k_fused(
    const float* __restrict__ x,
    const float* __restrict__ Wl1, const float* __restrict__ bl1,
    const float* __restrict__ Wr1, const float* __restrict__ br1,
    const void* __restrict__ ei, int N, int E) {
    __shared__ float sW[64 * 128];   // 32KB
    __shared__ float sXT[64 * 64];   // 16KB; reused as int scan buffer later
    int tid = threadIdx.x, b = blockIdx.x;
    int gthread = b * NT + tid;

    // phase 0a: zero counts
    for (int i = gthread; i < N; i += NB * NT) g_counts[i] = 0;

    // phase 0b: edge dtype detect (block 0 only)
    if (b == 0) {
        int* flag = (int*)sXT;
        if (tid == 0) flag[0] = 0;
        __syncthreads();
        const unsigned* p = (const unsigned*)ei;
        long long limit = 8192;
        long long tot = 4LL * E;   // 32-bit words if int64 view
        if (limit > tot) limit = tot;
        for (long long i = 2LL * tid + 1; i < limit; i += 2 * NT)
            if (p[i] != 0u) flag[0] = 1;
        __syncthreads();
        if (tid == 0) g_is64 = (flag[0] == 0) ? 1 : 0;
    }

    // phase 0c: gemm1 (independent of CSR). 1024 threads, one 64-row tile.
    for (int idx = tid; idx < 64 * 128; idx += NT) {
        int k = idx >> 7, j = idx & 127;
        sW[idx] = (j < 64) ? Wl1[k * 64 + j] : Wr1[k * 64 + (j - 64)];
    }
    __syncthreads();
    int cr = tid & 31, rr = tid >> 5;   // rr 0..31 = row-pair id
    int ntiles = (N + 63) >> 6;
    for (int t = b; t < ntiles; t += NB) {
        int row0 = t << 6;
        for (int idx = tid; idx < 64 * 64; idx += NT) {
            int r = idx >> 6, c = idx & 63;
            int gr = row0 + r;
            sXT[c * 64 + (r ^ (c & 30))] = (gr < N) ? x[gr * 64 + c] : 0.f;
        }
        __syncthreads();
        unsigned long long acc2[4] = {0ull, 0ull, 0ull, 0ull};
#pragma unroll 4
        for (int k = 0; k < 64; k++) {
            unsigned long long xv =
                *(const unsigned long long*)&sXT[k * 64 + ((2 * rr) ^ (k & 30))];
#pragma unroll
            for (int c = 0; c < 4; c++) {
                float w = sW[k * 128 + cr + 32 * c];
                acc2[c] = fma2(xv, pk2(w, w), acc2[c]);
            }
        }
        int r0 = row0 + 2 * rr;
#pragma unroll
        for (int c = 0; c < 4; c++) {
            int j = cr + 32 * c;
            float bq = (j < 64) ? bl1[j] : br1[j - 64];
            float2 v = unpk(acc2[c]);
            if (r0 < N) {
                float vv = v.x + bq;
                if (j < 64) g_xl1[r0 * 64 + j] = vv;
                else        g_xr1[r0 * 64 + (j - 64)] = vv;
            }
            if (r0 + 1 < N) {
                float vv = v.y + bq;
                if (j < 64) g_xl1[(r0 + 1) * 64 + j] = vv;
                else        g_xr1[(r0 + 1) * 64 + (j - 64)] = vv;
            }
        }
        __syncthreads();
    }
    gridbar();   // counts zeroed + is64 published

    // phase 1: histogram of dst
    int is64 = g_is64;
    for (int e = gthread; e < E; e += NB * NT) {
        int dn = load_idx(ei, is64, (long long)E + e);
        atomicAdd(&g_counts[dn], 1);
    }
    gridbar();

    // phase 2: scan (one element per thread; NB*NT=131072 >= N)
    int* ss = (int*)sXT;
    int i = gthread;
    int v = (i < N) ? g_counts[i] : 0;
    ss[tid] = v;
    __syncthreads();
    for (int off = 1; off < NT; off <<= 1) {
        int tmp = (tid >= off) ? ss[tid - off] : 0;
        __syncthreads();
        ss[tid] += tmp;
        __syncthreads();
    }
    int incl = ss[tid];
    if (tid == NT - 1) g_bsum[b] = incl;
    gridbar();
    if (b == 0) {
        int sv = (tid < NB) ? g_bsum[tid] : 0;
        __syncthreads();
        ss[tid] = sv;
        __syncthreads();
        for (int off = 1; off < NB; off <<= 1) {
            int tmp = (tid >= off && tid < NB) ? ss[tid - off] : 0;
            __syncthreads();
            if (tid < NB) ss[tid] += tmp;
            __syncthreads();
        }
        if (tid < NB) g_boff[tid] = ss[tid] - sv;   // exclusive
    }
    gridbar();
    int excl = incl - v + g_boff[b];
    if (i < N) { g_rowptr[i] = excl; g_wofs[i] = excl; }
    if (i == N - 1) g_rowptr[N] = excl + v;
    gridbar();

    // phase 3: scatter
    for (int e = gthread; e < E; e += NB * NT) {
        int dn = load_idx(ei, is64, (long long)E + e);
        int sn = load_idx(ei, is64, (long long)e);
        int pos = atomicAdd(&g_wofs[dn], 1);
        g_csr[pos] = sn;
    }
}

// ---------------- GEMM 2: h1[N,64] @ (Wl2|Wr2)[64,512] -> xl2(fp16), xr2(fp32)
__global__ __launch_bounds__(256) void k_gemm2(
    const float* __restrict__ Wl, const float* __restrict__ bl,
    const float* __restrict__ Wr, const float* __restrict__ br, int N) {
    __shared__ float sW[64 * 128];
    __shared__ float sXT[64 * 64];
    int tid = threadIdx.x;
    int colbase = blockIdx.y * 128;
    for (int idx = tid; idx < 64 * 128; idx += 256) {
        int k = idx >> 7, jj = idx & 127;
        int cg = colbase + jj;
        sW[idx] = (cg < 256) ? Wl[k * 256 + cg] : Wr[k * 256 + (cg - 256)];
    }
    int row0 = blockIdx.x * 64;
    for (int idx = tid; idx < 64 * 64; idx += 256) {
        int r = idx >> 6, c = idx & 63;
        int gr = row0 + r;
        sXT[c * 64 + (r ^ (c & 30))] = (gr < N) ? g_h1[gr * 64 + c] : 0.f;
    }
    __syncthreads();
    int cr = tid & 31, rr = tid >> 5;
    unsigned long long acc2[4][4];
#pragma unroll
    for (int p = 0; p < 4; p++)
#pragma unroll
        for (int c = 0; c < 4; c++) acc2[p][c] = 0ull;
#pragma unroll 4
    for (int k = 0; k < 64; k++) {
        unsigned long long wp[4];
#pragma unroll
        for (int c = 0; c < 4; c++) {
            float w = sW[k * 128 + cr + 32 * c];
            wp[c] = pk2(w, w);
        }
#pragma unroll
        for (int p = 0; p < 4; p++) {
            int r0 = rr * 8 + 2 * p;
            unsigned long long xv =
                *(const unsigned long long*)&sXT[k * 64 + (r0 ^ (k & 30))];
#pragma unroll
            for (int c = 0; c < 4; c++) acc2[p][c] = fma2(xv, wp[c], acc2[p][c]);
        }
    }
#pragma unroll
    for (int p = 0; p < 4; p++) {
        int r0 = row0 + rr * 8 + 2 * p;
#pragma unroll
        for (int c = 0; c < 4; c++) {
            int cg = colbase + cr + 32 * c;
            float b = (cg < 256) ? bl[cg] : br[cg - 256];
            float2 v = unpk(acc2[p][c]);
            if (r0 < N) {
                float vv = v.x + b;
                if (cg < 256) g_xl2h[r0 * 256 + cg] = __float2half_rn(vv);
                else          g_xr2[r0 * 256 + (cg - 256)] = vv;
            }
            if (r0 + 1 < N) {
                float vv = v.y + b;
                if (cg < 256) g_xl2h[(r0 + 1) * 256 + cg] = __float2half_rn(vv);
                else          g_xr2[(r0 + 1) * 256 + (cg - 256)] = vv;
            }
        }
    }
}

// ---------------- Layer 1 edge kernel (2-edge pipelined) ----------------
// Warp per dst node. Lane l owns elements {2l,2l+1}; head h = l>>3 (C=16).
// Self-loop peeled (defines softmax base m0); main loop does 2 edges/iter.
__global__ __launch_bounds__(256) void k_l1edge(
    const float* __restrict__ att, const float* __restrict__ bo, int N) {
    int warp = (blockIdx.x * blockDim.x + threadIdx.x) >> 5;
    int lane = threadIdx.x & 31;
    if (warp >= N) return;
    int i = warp;
    const int* __restrict__ csr = g_csr;
    float2 xr = *(const float2*)&g_xr1[i * 64 + 2 * lane];
    float2 a  = __ldg((const float2*)&att[2 * lane]);
    // self
    float2 xs = *(const float2*)&g_xl1[i * 64 + 2 * lane];
    float t0 = xs.x + xr.x; t0 = fmaxf(t0, 0.2f * t0);
    float t1 = xs.y + xr.y; t1 = fmaxf(t1, 0.2f * t1);
    float m0 = fmaf(a.x, t0, a.y * t1);
    m0 += __shfl_xor_sync(0xFFFFFFFFu, m0, 1);
    m0 += __shfl_xor_sync(0xFFFFFFFFu, m0, 2);
    m0 += __shfl_xor_sync(0xFFFFFFFFu, m0, 4);
    float d = 1.f, acc0 = xs.x, acc1 = xs.y;
    int beg = __ldg(&g_rowptr[i]), end = __ldg(&g_rowptr[i + 1]);
    int j = beg;
    for (; j + 1 < end; j += 2) {
        int s0 = __ldg(&csr[j]);
        int s1 = __ldg(&csr[j + 1]);
        float2 x0 = __ldg((const float2*)&g_xl1[s0 * 64 + 2 * lane]);
        float2 x1 = __ldg((const float2*)&g_xl1[s1 * 64 + 2 * lane]);
        float u0 = x0.x + xr.x; u0 = fmaxf(u0, 0.2f * u0);
        float u1 = x0.y + xr.y; u1 = fmaxf(u1, 0.2f * u1);
        float v0 = x1.x + xr.x; v0 = fmaxf(v0, 0.2f * v0);
        float v1 = x1.y + xr.y; v1 = fmaxf(v1, 0.2f * v1);
        float p0 = fmaf(a.x, u0, a.y * u1);
        float p1 = fmaf(a.x, v0, a.y * v1);
        p0 += __shfl_xor_sync(0xFFFFFFFFu, p0, 1);
        p1 += __shfl_xor_sync(0xFFFFFFFFu, p1, 1);
        p0 += __shfl_xor_sync(0xFFFFFFFFu, p0, 2);
        p1 += __shfl_xor_sync(0xFFFFFFFFu, p1, 2);
        p0 += __shfl_xor_sync(0xFFFFFFFFu, p0, 4);
        p1 += __shfl_xor_sync(0xFFFFFFFFu, p1, 4);
        float w0 = __expf(p0 - m0);
        float w1 = __expf(p1 - m0);
        d += w0 + w1;
        acc0 = fmaf(w0, x0.x, fmaf(w1, x1.x, acc0));
        acc1 = fmaf(w0, x0.y, fmaf(w1, x1.y, acc1));
    }
    if (j < end) {
        int s = __ldg(&csr[j]);
        float2 xl = __ldg((const float2*)&g_xl1[s * 64 + 2 * lane]);
        float u0 = xl.x + xr.x; u0 = fmaxf(u0, 0.2f * u0);
        float u1 = xl.y + xr.y; u1 = fmaxf(u1, 0.2f * u1);
        float p = fmaf(a.x, u0, a.y * u1);
        p += __shfl_xor_sync(0xFFFFFFFFu, p, 1);
        p += __shfl_xor_sync(0xFFFFFFFFu, p, 2);
        p += __shfl_xor_sync(0xFFFFFFFFu, p, 4);
        float w = __expf(p - m0);
        d += w;
        acc0 = fmaf(w, xl.x, acc0);
        acc1 = fmaf(w, xl.y, acc1);
    }
    float inv = 1.f / d;
    float2 bov = __ldg((const float2*)&bo[2 * lane]);
    float2 o;
    o.x = fmaxf(fmaf(acc0, inv, bov.x), 0.f);
    o.y = fmaxf(fmaf(acc1, inv, bov.y), 0.f);
    *(float2*)&g_h1[i * 64 + 2 * lane] = o;
}

// ---------------- Layer 2 edge kernel (2-edge pipelined) ----------------
__device__ __forceinline__ void cvt8(uint4 raw, float* xl) {
    float2 f;
    f = __half22float2(*reinterpret_cast<__half2*>(&raw.x)); xl[0] = f.x; xl[1] = f.y;
    f = __half22float2(*reinterpret_cast<__half2*>(&raw.y)); xl[2] = f.x; xl[3] = f.y;
    f = __half22float2(*reinterpret_cast<__half2*>(&raw.z)); xl[4] = f.x; xl[5] = f.y;
    f = __half22float2(*reinterpret_cast<__half2*>(&raw.w)); xl[6] = f.x; xl[7] = f.y;
}

__global__ __launch_bounds__(256) void k_l2edge(
    const float* __restrict__ att, const float* __restrict__ bo,
    float* __restrict__ out, int N) {
    int warp = (blockIdx.x * blockDim.x + threadIdx.x) >> 5;
    int lane = threadIdx.x & 31;
    if (warp >= N) return;
    int i = warp;
    const int* __restrict__ csr = g_csr;
    int h8 = lane * 8;
    float xr[8], av[8];
    {
        float4 r0 = *(const float4*)&g_xr2[i * 256 + h8];
        float4 r1 = *(const float4*)&g_xr2[i * 256 + h8 + 4];
        xr[0] = r0.x; xr[1] = r0.y; xr[2] = r0.z; xr[3] = r0.w;
        xr[4] = r1.x; xr[5] = r1.y; xr[6] = r1.z; xr[7] = r1.w;
        float4 a0 = __ldg((const float4*)&att[h8]);
        float4 a1 = __ldg((const float4*)&att[h8 + 4]);
        av[0] = a0.x; av[1] = a0.y; av[2] = a0.z; av[3] = a0.w;
        av[4] = a1.x; av[5] = a1.y; av[6] = a1.z; av[7] = a1.w;
    }
    // self (defines base m0)
    float acc[8], m0, d;
    {
        uint4 raw = __ldg((const uint4*)&g_xl2h[i * 256 + h8]);
        float xs[8];
        cvt8(raw, xs);
        float p = 0.f;
#pragma unroll
        for (int k = 0; k < 8; k++) {
            float t = xs[k] + xr[k];
            t = fmaxf(t, 0.2f * t);
            p = fmaf(av[k], t, p);
        }
        p += __shfl_xor_sync(0xFFFFFFFFu, p, 1);
        p += __shfl_xor_sync(0xFFFFFFFFu, p, 2);
        p += __shfl_xor_sync(0xFFFFFFFFu, p, 4);
        m0 = p; d = 1.f;
#pragma unroll
        for (int k = 0; k < 8; k++) acc[k] = xs[k];
    }
    int beg = __ldg(&g_rowptr[i]), end = __ldg(&g_rowptr[i + 1]);
    int j = beg;
    for (; j + 1 < end; j += 2) {
        int s0 = __ldg(&csr[j]);
        int s1 = __ldg(&csr[j + 1]);
        uint4 r0 = __ldg((const uint4*)&g_xl2h[s0 * 256 + h8]);
        uint4 r1 = __ldg((const uint4*)&g_xl2h[s1 * 256 + h8]);
        float x0[8], x1[8];
        cvt8(r0, x0);
        cvt8(r1, x1);
        float p0 = 0.f, p1 = 0.f;
#pragma unroll
        for (int k = 0; k < 8; k++) {
            float t0 = x0[k] + xr[k]; t0 = fmaxf(t0, 0.2f * t0);
            float t1 = x1[k] + xr[k]; t1 = fmaxf(t1, 0.2f * t1);
            p0 = fmaf(av[k], t0, p0);
            p1 = fmaf(av[k], t1, p1);
        }
        p0 += __shfl_xor_sync(0xFFFFFFFFu, p0, 1);
        p1 += __shfl_xor_sync(0xFFFFFFFFu, p1, 1);
        p0 += __shfl_xor_sync(0xFFFFFFFFu, p0, 2);
        p1 += __shfl_xor_sync(0xFFFFFFFFu, p1, 2);
        p0 += __shfl_xor_sync(0xFFFFFFFFu, p0, 4);
        p1 += __shfl_xor_sync(0xFFFFFFFFu, p1, 4);
        float w0 = __expf(p0 - m0);
        float w1 = __expf(p1 - m0);
        d += w0 + w1;
#pragma unroll
        for (int k = 0; k < 8; k++)
            acc[k] = fmaf(w0, x0[k], fmaf(w1, x1[k], acc[k]));
    }
    if (j < end) {
        int s = __ldg(&csr[j]);
        uint4 raw = __ldg((const uint4*)&g_xl2h[s * 256 + h8]);
        float xl[8];
        cvt8(raw, xl);
        float p = 0.f;
#pragma unroll
        for (int k = 0; k < 8; k++) {
            float t = xl[k] + xr[k];
            t = fmaxf(t, 0.2f * t);
            p = fmaf(av[k], t, p);
        }
        p += __shfl_xor_sync(0xFFFFFFFFu, p, 1);
        p += __shfl_xor_sync(0xFFFFFFFFu, p, 2);
        p += __shfl_xor_sync(0xFFFFFFFFu, p, 4);
        float w = __expf(p - m0);
        d += w;
#pragma unroll
        for (int k = 0; k < 8; k++) acc[k] = fmaf(w, xl[k], acc[k]);
    }
    float inv = 1.f / d;
    float r[8];
#pragma unroll
    for (int k = 0; k < 8; k++) r[k] = acc[k] * inv;
#pragma unroll
    for (int k = 0; k < 8; k++) r[k] += __shfl_xor_sync(0xFFFFFFFFu, r[k], 8);
#pragma unroll
    for (int k = 0; k < 8; k++) r[k] += __shfl_xor_sync(0xFFFFFFFFu, r[k], 16);
    if (lane < 8) {
        float4 b0 = __ldg((const float4*)&bo[h8]);
        float4 b1 = __ldg((const float4*)&bo[h8 + 4]);
        float4 o0, o1;
        o0.x = fmaxf(fmaf(0.25f, r[0], b0.x), 0.f);
        o0.y = fmaxf(fmaf(0.25f, r[1], b0.y), 0.f);
        o0.z = fmaxf(fmaf(0.25f, r[2], b0.z), 0.f);
        o0.w = fmaxf(fmaf(0.25f, r[3], b0.w), 0.f);
        o1.x = fmaxf(fmaf(0.25f, r[4], b1.x), 0.f);
        o1.y = fmaxf(fmaf(0.25f, r[5], b1.y), 0.f);
        o1.z = fmaxf(fmaf(0.25f, r[6], b1.z), 0.f);
        o1.w = fmaxf(fmaf(0.25f, r[7], b1.w), 0.f);
        *(float4*)&out[i * 64 + h8]     = o0;
        *(float4*)&out[i * 64 + h8 + 4] = o1;
    }
}

// ---------------- launch ----------------
extern "C" void kernel_launch(void* const* d_in, const int* in_sizes, int n_in,
                              void* d_out, int out_size) {
    const float* x   = (const float*)d_in[0];
    const void*  ei  = d_in[1];
    // d_in[2] = frame_mask (unused by the reference)
    const float* Wl1 = (const float*)d_in[3];
    const float* bl1 = (const float*)d_in[4];
    const float* Wr1 = (const float*)d_in[5];
    const float* br1 = (const float*)d_in[6];
    const float* att1 = (const float*)d_in[7];
    const float* bo1 = (const float*)d_in[8];
    const float* Wl2 = (const float*)d_in[9];
    const float* bl2 = (const float*)d_in[10];
    const float* Wr2 = (const float*)d_in[11];
    const float* br2 = (const float*)d_in[12];
    const float* att2 = (const float*)d_in[13];
    const float* bo2 = (const float*)d_in[14];

    int N = in_sizes[0] / 64;
    int E = in_sizes[1] / 2;
    if (N > NN) N = NN;
    if (E > EE) E = EE;

    // 1 launch: detect + zero + gemm1 + hist + scan + scatter (grid barriers)
    k_fused<<<NB, NT>>>(x, Wl1, bl1, Wr1, br1, ei, N, E);

    // layer 1 attention
    k_l1edge<<<(N + 7) / 8, 256>>>(att1, bo1, N);

    // layer 2 transform + attention
    int rb = (N + 63) / 64;
    dim3 g2(rb, 4);
    k_gemm2<<<g2, 256>>>(Wl2, bl2, Wr2, br2, N);
    k_l2edge<<<(N + 7) / 8, 256>>>(att2, bo2, (float*)d_out, N);
}

// round 13
// speedup vs baseline: 1.9311x; 1.0399x over previous
#include <cuda_runtime.h>
#include <cuda_fp16.h>
#include <math_constants.h>

#define NN 100000
#define EE 1600000
#define NB 128
#define NT 1024

// ---------------- device scratch (no allocation allowed) ----------------
__device__ __align__(16) float  g_xl1[NN * 64];
__device__ __align__(16) float  g_xr1[NN * 64];
__device__ __align__(16) float  g_h1 [NN * 64];
__device__ __align__(16) __half g_xl2h[NN * 256];   // fp16 gather table (51.2MB)
__device__ __align__(16) float  g_xr2[NN * 256];
__device__ int      g_counts[NN];
__device__ int      g_rowptr[NN + 1];
__device__ int      g_wofs[NN];
__device__ int      g_csr[EE];
__device__ int      g_bsum[NB];
__device__ int      g_boff[NB];
__device__ int      g_is64;
__device__ unsigned g_barcnt;     // zero-init
__device__ unsigned g_barphase;   // monotonically increasing across replays

// ---------------- f32x2 packed helpers ----------------
__device__ __forceinline__ unsigned long long pk2(float a, float b) {
    unsigned long long r;
    asm("mov.b64 %0, {%1, %2};" : "=l"(r) : "f"(a), "f"(b));
    return r;
}
__device__ __forceinline__ unsigned long long fma2(unsigned long long a,
                                                   unsigned long long b,
                                                   unsigned long long c) {
    unsigned long long d;
    asm("fma.rn.f32x2 %0, %1, %2, %3;" : "=l"(d) : "l"(a), "l"(b), "l"(c));
    return d;
}
__device__ __forceinline__ float2 unpk(unsigned long long v) {
    float2 f;
    asm("mov.b64 {%0, %1}, %2;" : "=f"(f.x), "=f"(f.y) : "l"(v));
    return f;
}

__device__ __forceinline__ int load_idx(const void* p, int is64, long long idx) {
    if (is64) return (int)(((const long long*)p)[idx]);
    return ((const int*)p)[idx];
}

// ---------------- grid barrier (sense via monotonic phase counter) ----------
__device__ __forceinline__ void gridbar() {
    __syncthreads();
    if (threadIdx.x == 0) {
        __threadfence();
        unsigned ph = *(volatile unsigned*)&g_barphase;
        if (atomicAdd(&g_barcnt, 1u) == NB - 1u) {
            g_barcnt = 0u;
            __threadfence();
            *(volatile unsigned*)&g_barphase = ph + 1u;
        } else {
            while (*(volatile unsigned*)&g_barphase == ph) {}
        }
        __threadfence();
    }
    __syncthreads();
}

// ---------------- fused: detect + zero + gemm1 | hist | scan ----------------
// 128 blocks x 1024 threads, all co-resident (1 block/SM on 148+ SMs).
__global__ __launch_bounds__(NT, 1) void k_fused(
    const float* __restrict__ x,
    const float* __restrict__ Wl1, const float* __restrict__ bl1,
    const float* __restrict__ Wr1, const float* __restrict__ br1,
    const void* __restrict__ ei, int N, int E) {
    __shared__ float sW[64 * 128];   // 32KB
    __shared__ float sXT[64 * 64];   // 16KB; reused as int scan buffer later
    int tid = threadIdx.x, b = blockIdx.x;
    int gthread = b * NT + tid;

    // phase 0a: zero counts
    for (int i = gthread; i < N; i += NB * NT) g_counts[i] = 0;

    // phase 0b: edge dtype detect (block 0 only)
    if (b == 0) {
        int* flag = (int*)sXT;
        if (tid == 0) flag[0] = 0;
        __syncthreads();
        const unsigned* p = (const unsigned*)ei;
        long long limit = 8192;
        long long tot = 4LL * E;   // 32-bit words if int64 view
        if (limit > tot) limit = tot;
        for (long long i = 2LL * tid + 1; i < limit; i += 2 * NT)
            if (p[i] != 0u) flag[0] = 1;
        __syncthreads();
        if (tid == 0) g_is64 = (flag[0] == 0) ? 1 : 0;
    }

    // phase 0c: gemm1 (independent of CSR). 1024 threads, one 64-row tile.
    for (int idx = tid; idx < 64 * 128; idx += NT) {
        int k = idx >> 7, j = idx & 127;
        sW[idx] = (j < 64) ? Wl1[k * 64 + j] : Wr1[k * 64 + (j - 64)];
    }
    __syncthreads();
    int cr = tid & 31, rr = tid >> 5;   // rr 0..31 = row-pair id
    int ntiles = (N + 63) >> 6;
    for (int t = b; t < ntiles; t += NB) {
        int row0 = t << 6;
        for (int idx = tid; idx < 64 * 64; idx += NT) {
            int r = idx >> 6, c = idx & 63;
            int gr = row0 + r;
            sXT[c * 64 + (r ^ (c & 30))] = (gr < N) ? x[gr * 64 + c] : 0.f;
        }
        __syncthreads();
        unsigned long long acc2[4] = {0ull, 0ull, 0ull, 0ull};
#pragma unroll 4
        for (int k = 0; k < 64; k++) {
            unsigned long long xv =
                *(const unsigned long long*)&sXT[k * 64 + ((2 * rr) ^ (k & 30))];
#pragma unroll
            for (int c = 0; c < 4; c++) {
                float w = sW[k * 128 + cr + 32 * c];
                acc2[c] = fma2(xv, pk2(w, w), acc2[c]);
            }
        }
        int r0 = row0 + 2 * rr;
#pragma unroll
        for (int c = 0; c < 4; c++) {
            int j = cr + 32 * c;
            float bq = (j < 64) ? bl1[j] : br1[j - 64];
            float2 v = unpk(acc2[c]);
            if (r0 < N) {
                float vv = v.x + bq;
                if (j < 64) g_xl1[r0 * 64 + j] = vv;
                else        g_xr1[r0 * 64 + (j - 64)] = vv;
            }
            if (r0 + 1 < N) {
                float vv = v.y + bq;
                if (j < 64) g_xl1[(r0 + 1) * 64 + j] = vv;
                else        g_xr1[(r0 + 1) * 64 + (j - 64)] = vv;
            }
        }
        __syncthreads();
    }
    gridbar();   // counts zeroed + is64 published

    // phase 1: histogram of dst
    int is64 = g_is64;
    for (int e = gthread; e < E; e += NB * NT) {
        int dn = load_idx(ei, is64, (long long)E + e);
        atomicAdd(&g_counts[dn], 1);
    }
    gridbar();

    // phase 2: scan (one element per thread; NB*NT=131072 >= N)
    int* ss = (int*)sXT;
    int i = gthread;
    int v = (i < N) ? g_counts[i] : 0;
    ss[tid] = v;
    __syncthreads();
    for (int off = 1; off < NT; off <<= 1) {
        int tmp = (tid >= off) ? ss[tid - off] : 0;
        __syncthreads();
        ss[tid] += tmp;
        __syncthreads();
    }
    int incl = ss[tid];
    if (tid == NT - 1) g_bsum[b] = incl;
    gridbar();
    if (b == 0) {
        int sv = (tid < NB) ? g_bsum[tid] : 0;
        __syncthreads();
        ss[tid] = sv;
        __syncthreads();
        for (int off = 1; off < NB; off <<= 1) {
            int tmp = (tid >= off && tid < NB) ? ss[tid - off] : 0;
            __syncthreads();
            if (tid < NB) ss[tid] += tmp;
            __syncthreads();
        }
        if (tid < NB) g_boff[tid] = ss[tid] - sv;   // exclusive
    }
    gridbar();
    int excl = incl - v + g_boff[b];
    if (i < N) { g_rowptr[i] = excl; g_wofs[i] = excl; }
    if (i == N - 1) g_rowptr[N] = excl + v;
    // scatter moved to its own kernel (kernel boundary = sync)
}

// ---------------- scatter (standalone so the ncu slot lands on gemm2) -------
__global__ void k_scatter(const void* __restrict__ ei, int E) {
    int e = blockIdx.x * blockDim.x + threadIdx.x;
    if (e >= E) return;
    int is64 = g_is64;
    int dn = load_idx(ei, is64, (long long)E + e);
    int sn = load_idx(ei, is64, (long long)e);
    int pos = atomicAdd(&g_wofs[dn], 1);
    g_csr[pos] = sn;
}

// ---------------- Layer 1 edge kernel (2-edge, dual-dot leaky) --------------
// Warp per dst node. Lane l owns elements {2l,2l+1}; head h = l>>3 (C=16).
// leaky(t)=0.6t+0.4|t| -> score = 0.6*dot(a,t)+0.4*dot(a,|t|), |t| free in FFMA.
// Accumulate w*t; epilogue: out = acc/d - xr (exact identity).
__global__ __launch_bounds__(256) void k_l1edge(
    const float* __restrict__ att, const float* __restrict__ bo, int N) {
    int warp = (blockIdx.x * blockDim.x + threadIdx.x) >> 5;
    int lane = threadIdx.x & 31;
    if (warp >= N) return;
    int i = warp;
    const int* __restrict__ csr = g_csr;
    float2 xr = *(const float2*)&g_xr1[i * 64 + 2 * lane];
    float2 a  = __ldg((const float2*)&att[2 * lane]);
    // self edge (defines softmax base m0)
    float2 xs = *(const float2*)&g_xl1[i * 64 + 2 * lane];
    float ts0 = xs.x + xr.x, ts1 = xs.y + xr.y;
    float pa = fmaf(a.x, ts0, a.y * ts1);
    float pb = fmaf(a.x, fabsf(ts0), a.y * fabsf(ts1));
    float m0 = fmaf(0.6f, pa, 0.4f * pb);
    m0 += __shfl_xor_sync(0xFFFFFFFFu, m0, 1);
    m0 += __shfl_xor_sync(0xFFFFFFFFu, m0, 2);
    m0 += __shfl_xor_sync(0xFFFFFFFFu, m0, 4);
    float d = 1.f, acc0 = ts0, acc1 = ts1;
    int beg = __ldg(&g_rowptr[i]), end = __ldg(&g_rowptr[i + 1]);
    int j = beg;
    for (; j + 1 < end; j += 2) {
        int s0 = __ldg(&csr[j]);
        int s1 = __ldg(&csr[j + 1]);
        float2 x0 = __ldg((const float2*)&g_xl1[s0 * 64 + 2 * lane]);
        float2 x1 = __ldg((const float2*)&g_xl1[s1 * 64 + 2 * lane]);
        float u0 = x0.x + xr.x, u1 = x0.y + xr.y;
        float v0 = x1.x + xr.x, v1 = x1.y + xr.y;
        float pa0 = fmaf(a.x, u0, a.y * u1);
        float pb0 = fmaf(a.x, fabsf(u0), a.y * fabsf(u1));
        float pa1 = fmaf(a.x, v0, a.y * v1);
        float pb1 = fmaf(a.x, fabsf(v0), a.y * fabsf(v1));
        float p0 = fmaf(0.6f, pa0, 0.4f * pb0);
        float p1 = fmaf(0.6f, pa1, 0.4f * pb1);
        p0 += __shfl_xor_sync(0xFFFFFFFFu, p0, 1);
        p1 += __shfl_xor_sync(0xFFFFFFFFu, p1, 1);
        p0 += __shfl_xor_sync(0xFFFFFFFFu, p0, 2);
        p1 += __shfl_xor_sync(0xFFFFFFFFu, p1, 2);
        p0 += __shfl_xor_sync(0xFFFFFFFFu, p0, 4);
        p1 += __shfl_xor_sync(0xFFFFFFFFu, p1, 4);
        float w0 = __expf(p0 - m0);
        float w1 = __expf(p1 - m0);
        d += w0 + w1;
        acc0 = fmaf(w0, u0, fmaf(w1, v0, acc0));
        acc1 = fmaf(w0, u1, fmaf(w1, v1, acc1));
    }
    if (j < end) {
        int s = __ldg(&csr[j]);
        float2 xl = __ldg((const float2*)&g_xl1[s * 64 + 2 * lane]);
        float u0 = xl.x + xr.x, u1 = xl.y + xr.y;
        float pa1 = fmaf(a.x, u0, a.y * u1);
        float pb1 = fmaf(a.x, fabsf(u0), a.y * fabsf(u1));
        float p = fmaf(0.6f, pa1, 0.4f * pb1);
        p += __shfl_xor_sync(0xFFFFFFFFu, p, 1);
        p += __shfl_xor_sync(0xFFFFFFFFu, p, 2);
        p += __shfl_xor_sync(0xFFFFFFFFu, p, 4);
        float w = __expf(p - m0);
        d += w;
        acc0 = fmaf(w, u0, acc0);
        acc1 = fmaf(w, u1, acc1);
    }
    float inv = 1.f / d;
    float2 bov = __ldg((const float2*)&bo[2 * lane]);
    float2 o;
    o.x = fmaxf(fmaf(acc0, inv, bov.x - xr.x), 0.f);   // acc/d - xr + bo
    o.y = fmaxf(fmaf(acc1, inv, bov.y - xr.y), 0.f);
    *(float2*)&g_h1[i * 64 + 2 * lane] = o;
}

// ---------------- GEMM 2: h1[N,64] @ (Wl2|Wr2)[64,512] -> xl2(fp16), xr2(fp32)
__global__ __launch_bounds__(256) void k_gemm2(
    const float* __restrict__ Wl, const float* __restrict__ bl,
    const float* __restrict__ Wr, const float* __restrict__ br, int N) {
    __shared__ float sW[64 * 128];
    __shared__ float sXT[64 * 64];
    int tid = threadIdx.x;
    int colbase = blockIdx.y * 128;
    for (int idx = tid; idx < 64 * 128; idx += 256) {
        int k = idx >> 7, jj = idx & 127;
        int cg = colbase + jj;
        sW[idx] = (cg < 256) ? Wl[k * 256 + cg] : Wr[k * 256 + (cg - 256)];
    }
    int row0 = blockIdx.x * 64;
    for (int idx = tid; idx < 64 * 64; idx += 256) {
        int r = idx >> 6, c = idx & 63;
        int gr = row0 + r;
        sXT[c * 64 + (r ^ (c & 30))] = (gr < N) ? g_h1[gr * 64 + c] : 0.f;
    }
    __syncthreads();
    int cr = tid & 31, rr = tid >> 5;
    unsigned long long acc2[4][4];
#pragma unroll
    for (int p = 0; p < 4; p++)
#pragma unroll
        for (int c = 0; c < 4; c++) acc2[p][c] = 0ull;
#pragma unroll 4
    for (int k = 0; k < 64; k++) {
        unsigned long long wp[4];
#pragma unroll
        for (int c = 0; c < 4; c++) {
            float w = sW[k * 128 + cr + 32 * c];
            wp[c] = pk2(w, w);
        }
#pragma unroll
        for (int p = 0; p < 4; p++) {
            int r0 = rr * 8 + 2 * p;
            unsigned long long xv =
                *(const unsigned long long*)&sXT[k * 64 + (r0 ^ (k & 30))];
#pragma unroll
            for (int c = 0; c < 4; c++) acc2[p][c] = fma2(xv, wp[c], acc2[p][c]);
        }
    }
#pragma unroll
    for (int p = 0; p < 4; p++) {
        int r0 = row0 + rr * 8 + 2 * p;
#pragma unroll
        for (int c = 0; c < 4; c++) {
            int cg = colbase + cr + 32 * c;
            float b = (cg < 256) ? bl[cg] : br[cg - 256];
            float2 v = unpk(acc2[p][c]);
            if (r0 < N) {
                float vv = v.x + b;
                if (cg < 256) g_xl2h[r0 * 256 + cg] = __float2half_rn(vv);
                else          g_xr2[r0 * 256 + (cg - 256)] = vv;
            }
            if (r0 + 1 < N) {
                float vv = v.y + b;
                if (cg < 256) g_xl2h[(r0 + 1) * 256 + cg] = __float2half_rn(vv);
                else          g_xr2[(r0 + 1) * 256 + (cg - 256)] = vv;
            }
        }
    }
}

// ---------------- Layer 2 edge kernel (2-edge, hadd2 + dual-dot) ------------
// Warp per dst node. Lane l owns elements {8l..8l+7}; head h = l>>3 (C=64).
// t formed in half2 (xl fp16 + xr fp16): 4 HADD2 -> 8 cvt. Dual-dot with free
// |t|; accumulate w*t; epilogue subtracts xr_fp16 exactly: r = acc/d - xr16.
__device__ __forceinline__ void cvt8h(const __half2* t, float* f) {
    float2 q;
    q = __half22float2(t[0]); f[0] = q.x; f[1] = q.y;
    q = __half22float2(t[1]); f[2] = q.x; f[3] = q.y;
    q = __half22float2(t[2]); f[4] = q.x; f[5] = q.y;
    q = __half22float2(t[3]); f[6] = q.x; f[7] = q.y;
}

__global__ __launch_bounds__(256, 4) void k_l2edge(
    const float* __restrict__ att, const float* __restrict__ bo,
    float* __restrict__ out, int N) {
    int warp = (blockIdx.x * blockDim.x + threadIdx.x) >> 5;
    int lane = threadIdx.x & 31;
    if (warp >= N) return;
    int i = warp;
    const int* __restrict__ csr = g_csr;
    int h8 = lane * 8;
    __half2 xrh[4];
    float av[8];
    {
        float4 r0 = *(const float4*)&g_xr2[i * 256 + h8];
        float4 r1 = *(const float4*)&g_xr2[i * 256 + h8 + 4];
        xrh[0] = __floats2half2_rn(r0.x, r0.y);
        xrh[1] = __floats2half2_rn(r0.z, r0.w);
        xrh[2] = __floats2half2_rn(r1.x, r1.y);
        xrh[3] = __floats2half2_rn(r1.z, r1.w);
        float4 a0 = __ldg((const float4*)&att[h8]);
        float4 a1 = __ldg((const float4*)&att[h8 + 4]);
        av[0] = a0.x; av[1] = a0.y; av[2] = a0.z; av[3] = a0.w;
        av[4] = a1.x; av[5] = a1.y; av[6] = a1.z; av[7] = a1.w;
    }
    // self edge: base m0, w=1
    float acc[8], m0, d;
    {
        uint4 raw = __ldg((const uint4*)&g_xl2h[i * 256 + h8]);
        __half2 th[4];
        const __half2* xh = (const __half2*)&raw;
#pragma unroll
        for (int q = 0; q < 4; q++) th[q] = __hadd2(xh[q], xrh[q]);
        float t[8];
        cvt8h(th, t);
        float pa = 0.f, pb = 0.f;
#pragma unroll
        for (int k = 0; k < 8; k++) {
            pa = fmaf(av[k], t[k], pa);
            pb = fmaf(av[k], fabsf(t[k]), pb);
        }
        float p = fmaf(0.6f, pa, 0.4f * pb);
        p += __shfl_xor_sync(0xFFFFFFFFu, p, 1);
        p += __shfl_xor_sync(0xFFFFFFFFu, p, 2);
        p += __shfl_xor_sync(0xFFFFFFFFu, p, 4);
        m0 = p; d = 1.f;
#pragma unroll
        for (int k = 0; k < 8; k++) acc[k] = t[k];
    }
    int beg = __ldg(&g_rowptr[i]), end = __ldg(&g_rowptr[i + 1]);
    int j = beg;
    for (; j + 1 < end; j += 2) {
        int s0 = __ldg(&csr[j]);
        int s1 = __ldg(&csr[j + 1]);
        uint4 r0 = __ldg((const uint4*)&g_xl2h[s0 * 256 + h8]);
        uint4 r1 = __ldg((const uint4*)&g_xl2h[s1 * 256 + h8]);
        __half2 t0h[4], t1h[4];
        const __half2* x0h = (const __half2*)&r0;
        const __half2* x1h = (const __half2*)&r1;
#pragma unroll
        for (int q = 0; q < 4; q++) {
            t0h[q] = __hadd2(x0h[q], xrh[q]);
            t1h[q] = __hadd2(x1h[q], xrh[q]);
        }
        float t0[8], t1[8];
        cvt8h(t0h, t0);
        cvt8h(t1h, t1);
        float pa0 = 0.f, pb0 = 0.f, pa1 = 0.f, pb1 = 0.f;
#pragma unroll
        for (int k = 0; k < 8; k++) {
            pa0 = fmaf(av[k], t0[k], pa0);
            pb0 = fmaf(av[k], fabsf(t0[k]), pb0);
            pa1 = fmaf(av[k], t1[k], pa1);
            pb1 = fmaf(av[k], fabsf(t1[k]), pb1);
        }
        float p0 = fmaf(0.6f, pa0, 0.4f * pb0);
        float p1 = fmaf(0.6f, pa1, 0.4f * pb1);
        p0 += __shfl_xor_sync(0xFFFFFFFFu, p0, 1);
        p1 += __shfl_xor_sync(0xFFFFFFFFu, p1, 1);
        p0 += __shfl_xor_sync(0xFFFFFFFFu, p0, 2);
        p1 += __shfl_xor_sync(0xFFFFFFFFu, p1, 2);
        p0 += __shfl_xor_sync(0xFFFFFFFFu, p0, 4);
        p1 += __shfl_xor_sync(0xFFFFFFFFu, p1, 4);
        float w0 = __expf(p0 - m0);
        float w1 = __expf(p1 - m0);
        d += w0 + w1;
#pragma unroll
        for (int k = 0; k < 8; k++)
            acc[k] = fmaf(w0, t0[k], fmaf(w1, t1[k], acc[k]));
    }
    if (j < end) {
        int s = __ldg(&csr[j]);
        uint4 raw = __ldg((const uint4*)&g_xl2h[s * 256 + h8]);
        __half2 th[4];
        const __half2* xh = (const __half2*)&raw;
#pragma unroll
        for (int q = 0; q < 4; q++) th[q] = __hadd2(xh[q], xrh[q]);
        float t[8];
        cvt8h(th, t);
        float pa = 0.f, pb = 0.f;
#pragma unroll
        for (int k = 0; k < 8; k++) {
            pa = fmaf(av[k], t[k], pa);
            pb = fmaf(av[k], fabsf(t[k]), pb);
        }
        float p = fmaf(0.6f, pa, 0.4f * pb);
        p += __shfl_xor_sync(0xFFFFFFFFu, p, 1);
        p += __shfl_xor_sync(0xFFFFFFFFu, p, 2);
        p += __shfl_xor_sync(0xFFFFFFFFu, p, 4);
        float w = __expf(p - m0);
        d += w;
#pragma unroll
        for (int k = 0; k < 8; k++) acc[k] = fmaf(w, t[k], acc[k]);
    }
    // epilogue: r = acc/d - xr16 (exact), then mean over heads
    float inv = 1.f / d;
    float xrr[8];
    cvt8h(xrh, xrr);
    float r[8];
#pragma unroll
    for (int k = 0; k < 8; k++) r[k] = fmaf(acc[k], inv, -xrr[k]);
#pragma unroll
    for (int k = 0; k < 8; k++) r[k] += __shfl_xor_sync(0xFFFFFFFFu, r[k], 8);
#pragma unroll
    for (int k = 0; k < 8; k++) r[k] += __shfl_xor_sync(0xFFFFFFFFu, r[k], 16);
    if (lane < 8) {
        float4 b0 = __ldg((const float4*)&bo[h8]);
        float4 b1 = __ldg((const float4*)&bo[h8 + 4]);
        float4 o0, o1;
        o0.x = fmaxf(fmaf(0.25f, r[0], b0.x), 0.f);
        o0.y = fmaxf(fmaf(0.25f, r[1], b0.y), 0.f);
        o0.z = fmaxf(fmaf(0.25f, r[2], b0.z), 0.f);
        o0.w = fmaxf(fmaf(0.25f, r[3], b0.w), 0.f);
        o1.x = fmaxf(fmaf(0.25f, r[4], b1.x), 0.f);
        o1.y = fmaxf(fmaf(0.25f, r[5], b1.y), 0.f);
        o1.z = fmaxf(fmaf(0.25f, r[6], b1.z), 0.f);
        o1.w = fmaxf(fmaf(0.25f, r[7], b1.w), 0.f);
        *(float4*)&out[i * 64 + h8]     = o0;
        *(float4*)&out[i * 64 + h8 + 4] = o1;
    }
}

// ---------------- launch ----------------
extern "C" void kernel_launch(void* const* d_in, const int* in_sizes, int n_in,
                              void* d_out, int out_size) {
    const float* x   = (const float*)d_in[0];
    const void*  ei  = d_in[1];
    // d_in[2] = frame_mask (unused by the reference)
    const float* Wl1 = (const float*)d_in[3];
    const float* bl1 = (const float*)d_in[4];
    const float* Wr1 = (const float*)d_in[5];
    const float* br1 = (const float*)d_in[6];
    const float* att1 = (const float*)d_in[7];
    const float* bo1 = (const float*)d_in[8];
    const float* Wl2 = (const float*)d_in[9];
    const float* bl2 = (const float*)d_in[10];
    const float* Wr2 = (const float*)d_in[11];
    const float* br2 = (const float*)d_in[12];
    const float* att2 = (const float*)d_in[13];
    const float* bo2 = (const float*)d_in[14];

    int N = in_sizes[0] / 64;
    int E = in_sizes[1] / 2;
    if (N > NN) N = NN;
    if (E > EE) E = EE;

    // launch 0: detect + zero + gemm1 + hist + scan (grid barriers inside)
    k_fused<<<NB, NT>>>(x, Wl1, bl1, Wr1, br1, ei, N, E);
    // launch 1: CSR scatter
    k_scatter<<<(E + 255) / 256, 256>>>(ei, E);
    // launch 2: layer-1 attention
    k_l1edge<<<(N + 7) / 8, 256>>>(att1, bo1, N);
    // launch 3 (ncu slot): layer-2 transform
    int rb = (N + 63) / 64;
    dim3 g2(rb, 4);
    k_gemm2<<<g2, 256>>>(Wl2, bl2, Wr2, br2, N);
    // launch 4: layer-2 attention
    k_l2edge<<<(N + 7) / 8, 256>>>(att2, bo2, (float*)d_out, N);
}

// round 14
// speedup vs baseline: 2.4671x; 1.2776x over previous
#include <cuda_runtime.h>
#include <cuda_fp16.h>
#include <math_constants.h>

#define NN 100000
#define EE 1600000
#define NB 128
#define NT 1024

// ---------------- device scratch (no allocation allowed) ----------------
__device__ __align__(16) float  g_xl1[NN * 64];
__device__ __align__(16) float  g_xr1[NN * 64];
__device__ __align__(16) float  g_h1 [NN * 64];
__device__ __align__(16) __half g_xl2h[NN * 256];   // fp16 gather table (51.2MB)
__device__ __align__(16) float  g_xr2[NN * 256];
__device__ int      g_counts[NN];
__device__ int      g_rowptr[NN + 1];
__device__ int      g_wofs[NN];
__device__ int      g_csr[EE];
__device__ int      g_bsum[NB];
__device__ int      g_boff[NB];
__device__ int      g_is64;
__device__ unsigned g_barcnt;     // zero-init
__device__ unsigned g_barphase;   // monotonically increasing across replays

// ---------------- f32x2 packed helpers (gemm1) ----------------
__device__ __forceinline__ unsigned long long pk2(float a, float b) {
    unsigned long long r;
    asm("mov.b64 %0, {%1, %2};" : "=l"(r) : "f"(a), "f"(b));
    return r;
}
__device__ __forceinline__ unsigned long long fma2(unsigned long long a,
                                                   unsigned long long b,
                                                   unsigned long long c) {
    unsigned long long d;
    asm("fma.rn.f32x2 %0, %1, %2, %3;" : "=l"(d) : "l"(a), "l"(b), "l"(c));
    return d;
}
__device__ __forceinline__ float2 unpk(unsigned long long v) {
    float2 f;
    asm("mov.b64 {%0, %1}, %2;" : "=f"(f.x), "=f"(f.y) : "l"(v));
    return f;
}

__device__ __forceinline__ int load_idx(const void* p, int is64, long long idx) {
    if (is64) return (int)(((const long long*)p)[idx]);
    return ((const int*)p)[idx];
}

// ---------------- tensor-core helpers (gemm2) ----------------
__device__ __forceinline__ unsigned smem_u32(const void* p) {
    return (unsigned)__cvta_generic_to_shared(p);
}
__device__ __forceinline__ void ldm4(unsigned* r, unsigned addr) {
    asm volatile("ldmatrix.sync.aligned.m8n8.x4.shared.b16 {%0,%1,%2,%3}, [%4];"
        : "=r"(r[0]), "=r"(r[1]), "=r"(r[2]), "=r"(r[3]) : "r"(addr));
}
__device__ __forceinline__ void mma16816(float* c, const unsigned* a,
                                         unsigned b0, unsigned b1) {
    asm volatile("mma.sync.aligned.m16n8k16.row.col.f32.f16.f16.f32 "
        "{%0,%1,%2,%3}, {%4,%5,%6,%7}, {%8,%9}, {%0,%1,%2,%3};"
        : "+f"(c[0]), "+f"(c[1]), "+f"(c[2]), "+f"(c[3])
        : "r"(a[0]), "r"(a[1]), "r"(a[2]), "r"(a[3]), "r"(b0), "r"(b1));
}

// ---------------- grid barrier (sense via monotonic phase counter) ----------
__device__ __forceinline__ void gridbar() {
    __syncthreads();
    if (threadIdx.x == 0) {
        __threadfence();
        unsigned ph = *(volatile unsigned*)&g_barphase;
        if (atomicAdd(&g_barcnt, 1u) == NB - 1u) {
            g_barcnt = 0u;
            __threadfence();
            *(volatile unsigned*)&g_barphase = ph + 1u;
        } else {
            while (*(volatile unsigned*)&g_barphase == ph) {}
        }
        __threadfence();
    }
    __syncthreads();
}

// ---------------- fused: detect + zero + gemm1 | hist | scan ----------------
__global__ __launch_bounds__(NT, 1) void k_fused(
    const float* __restrict__ x,
    const float* __restrict__ Wl1, const float* __restrict__ bl1,
    const float* __restrict__ Wr1, const float* __restrict__ br1,
    const void* __restrict__ ei, int N, int E) {
    __shared__ float sW[64 * 128];   // 32KB
    __shared__ float sXT[64 * 64];   // 16KB; reused as int scan buffer later
    int tid = threadIdx.x, b = blockIdx.x;
    int gthread = b * NT + tid;

    // phase 0a: zero counts
    for (int i = gthread; i < N; i += NB * NT) g_counts[i] = 0;

    // phase 0b: edge dtype detect (block 0 only)
    if (b == 0) {
        int* flag = (int*)sXT;
        if (tid == 0) flag[0] = 0;
        __syncthreads();
        const unsigned* p = (const unsigned*)ei;
        long long limit = 8192;
        long long tot = 4LL * E;   // 32-bit words if int64 view
        if (limit > tot) limit = tot;
        for (long long i = 2LL * tid + 1; i < limit; i += 2 * NT)
            if (p[i] != 0u) flag[0] = 1;
        __syncthreads();
        if (tid == 0) g_is64 = (flag[0] == 0) ? 1 : 0;
    }

    // phase 0c: gemm1. 1024 threads, one 64-row tile at a time.
    for (int idx = tid; idx < 64 * 128; idx += NT) {
        int k = idx >> 7, j = idx & 127;
        sW[idx] = (j < 64) ? Wl1[k * 64 + j] : Wr1[k * 64 + (j - 64)];
    }
    __syncthreads();
    int cr = tid & 31, rr = tid >> 5;   // rr 0..31 = row-pair id
    int ntiles = (N + 63) >> 6;
    for (int t = b; t < ntiles; t += NB) {
        int row0 = t << 6;
        for (int idx = tid; idx < 64 * 64; idx += NT) {
            int r = idx >> 6, c = idx & 63;
            int gr = row0 + r;
            sXT[c * 64 + (r ^ (c & 30))] = (gr < N) ? x[gr * 64 + c] : 0.f;
        }
        __syncthreads();
        unsigned long long acc2[4] = {0ull, 0ull, 0ull, 0ull};
#pragma unroll 4
        for (int k = 0; k < 64; k++) {
            unsigned long long xv =
                *(const unsigned long long*)&sXT[k * 64 + ((2 * rr) ^ (k & 30))];
#pragma unroll
            for (int c = 0; c < 4; c++) {
                float w = sW[k * 128 + cr + 32 * c];
                acc2[c] = fma2(xv, pk2(w, w), acc2[c]);
            }
        }
        int r0 = row0 + 2 * rr;
#pragma unroll
        for (int c = 0; c < 4; c++) {
            int j = cr + 32 * c;
            float bq = (j < 64) ? bl1[j] : br1[j - 64];
            float2 v = unpk(acc2[c]);
            if (r0 < N) {
                float vv = v.x + bq;
                if (j < 64) g_xl1[r0 * 64 + j] = vv;
                else        g_xr1[r0 * 64 + (j - 64)] = vv;
            }
            if (r0 + 1 < N) {
                float vv = v.y + bq;
                if (j < 64) g_xl1[(r0 + 1) * 64 + j] = vv;
                else        g_xr1[(r0 + 1) * 64 + (j - 64)] = vv;
            }
        }
        __syncthreads();
    }
    gridbar();   // counts zeroed + is64 published

    // phase 1: histogram of dst
    int is64 = g_is64;
    for (int e = gthread; e < E; e += NB * NT) {
        int dn = load_idx(ei, is64, (long long)E + e);
        atomicAdd(&g_counts[dn], 1);
    }
    gridbar();

    // phase 2: scan (one element per thread; NB*NT=131072 >= N)
    int* ss = (int*)sXT;
    int i = gthread;
    int v = (i < N) ? g_counts[i] : 0;
    ss[tid] = v;
    __syncthreads();
    for (int off = 1; off < NT; off <<= 1) {
        int tmp = (tid >= off) ? ss[tid - off] : 0;
        __syncthreads();
        ss[tid] += tmp;
        __syncthreads();
    }
    int incl = ss[tid];
    if (tid == NT - 1) g_bsum[b] = incl;
    gridbar();
    if (b == 0) {
        int sv = (tid < NB) ? g_bsum[tid] : 0;
        __syncthreads();
        ss[tid] = sv;
        __syncthreads();
        for (int off = 1; off < NB; off <<= 1) {
            int tmp = (tid >= off && tid < NB) ? ss[tid - off] : 0;
            __syncthreads();
            if (tid < NB) ss[tid] += tmp;
            __syncthreads();
        }
        if (tid < NB) g_boff[tid] = ss[tid] - sv;   // exclusive
    }
    gridbar();
    int excl = incl - v + g_boff[b];
    if (i < N) { g_rowptr[i] = excl; g_wofs[i] = excl; }
    if (i == N - 1) g_rowptr[N] = excl + v;
}

// ---------------- scatter ----------------
__global__ void k_scatter(const void* __restrict__ ei, int E) {
    int e = blockIdx.x * blockDim.x + threadIdx.x;
    if (e >= E) return;
    int is64 = g_is64;
    int dn = load_idx(ei, is64, (long long)E + e);
    int sn = load_idx(ei, is64, (long long)e);
    int pos = atomicAdd(&g_wofs[dn], 1);
    g_csr[pos] = sn;
}

// ---------------- Layer 1 edge kernel (2-edge, dual-dot leaky) --------------
__global__ __launch_bounds__(256) void k_l1edge(
    const float* __restrict__ att, const float* __restrict__ bo, int N) {
    int warp = (blockIdx.x * blockDim.x + threadIdx.x) >> 5;
    int lane = threadIdx.x & 31;
    if (warp >= N) return;
    int i = warp;
    const int* __restrict__ csr = g_csr;
    float2 xr = *(const float2*)&g_xr1[i * 64 + 2 * lane];
    float2 a  = __ldg((const float2*)&att[2 * lane]);
    float2 xs = *(const float2*)&g_xl1[i * 64 + 2 * lane];
    float ts0 = xs.x + xr.x, ts1 = xs.y + xr.y;
    float pa = fmaf(a.x, ts0, a.y * ts1);
    float pb = fmaf(a.x, fabsf(ts0), a.y * fabsf(ts1));
    float m0 = fmaf(0.6f, pa, 0.4f * pb);
    m0 += __shfl_xor_sync(0xFFFFFFFFu, m0, 1);
    m0 += __shfl_xor_sync(0xFFFFFFFFu, m0, 2);
    m0 += __shfl_xor_sync(0xFFFFFFFFu, m0, 4);
    float d = 1.f, acc0 = ts0, acc1 = ts1;
    int beg = __ldg(&g_rowptr[i]), end = __ldg(&g_rowptr[i + 1]);
    int j = beg;
    for (; j + 1 < end; j += 2) {
        int s0 = __ldg(&csr[j]);
        int s1 = __ldg(&csr[j + 1]);
        float2 x0 = __ldg((const float2*)&g_xl1[s0 * 64 + 2 * lane]);
        float2 x1 = __ldg((const float2*)&g_xl1[s1 * 64 + 2 * lane]);
        float u0 = x0.x + xr.x, u1 = x0.y + xr.y;
        float v0 = x1.x + xr.x, v1 = x1.y + xr.y;
        float pa0 = fmaf(a.x, u0, a.y * u1);
        float pb0 = fmaf(a.x, fabsf(u0), a.y * fabsf(u1));
        float pa1 = fmaf(a.x, v0, a.y * v1);
        float pb1 = fmaf(a.x, fabsf(v0), a.y * fabsf(v1));
        float p0 = fmaf(0.6f, pa0, 0.4f * pb0);
        float p1 = fmaf(0.6f, pa1, 0.4f * pb1);
        p0 += __shfl_xor_sync(0xFFFFFFFFu, p0, 1);
        p1 += __shfl_xor_sync(0xFFFFFFFFu, p1, 1);
        p0 += __shfl_xor_sync(0xFFFFFFFFu, p0, 2);
        p1 += __shfl_xor_sync(0xFFFFFFFFu, p1, 2);
        p0 += __shfl_xor_sync(0xFFFFFFFFu, p0, 4);
        p1 += __shfl_xor_sync(0xFFFFFFFFu, p1, 4);
        float w0 = __expf(p0 - m0);
        float w1 = __expf(p1 - m0);
        d += w0 + w1;
        acc0 = fmaf(w0, u0, fmaf(w1, v0, acc0));
        acc1 = fmaf(w0, u1, fmaf(w1, v1, acc1));
    }
    if (j < end) {
        int s = __ldg(&csr[j]);
        float2 xl = __ldg((const float2*)&g_xl1[s * 64 + 2 * lane]);
        float u0 = xl.x + xr.x, u1 = xl.y + xr.y;
        float pa1 = fmaf(a.x, u0, a.y * u1);
        float pb1 = fmaf(a.x, fabsf(u0), a.y * fabsf(u1));
        float p = fmaf(0.6f, pa1, 0.4f * pb1);
        p += __shfl_xor_sync(0xFFFFFFFFu, p, 1);
        p += __shfl_xor_sync(0xFFFFFFFFu, p, 2);
        p += __shfl_xor_sync(0xFFFFFFFFu, p, 4);
        float w = __expf(p - m0);
        d += w;
        acc0 = fmaf(w, u0, acc0);
        acc1 = fmaf(w, u1, acc1);
    }
    float inv = 1.f / d;
    float2 bov = __ldg((const float2*)&bo[2 * lane]);
    float2 o;
    o.x = fmaxf(fmaf(acc0, inv, bov.x - xr.x), 0.f);
    o.y = fmaxf(fmaf(acc1, inv, bov.y - xr.y), 0.f);
    *(float2*)&g_h1[i * 64 + 2 * lane] = o;
}

// ---------------- GEMM 2 (tensor cores): h1 @ (Wl2|Wr2) -> xl2h, xr2 --------
// fp16 HMMA m16n8k16, fp32 accumulate. Block tile 128x128, K=64 (4 k-steps).
// 8 warps = 2(m) x 4(n); per warp 4 m-tiles x 4 n-tiles.
// sA[row][k] row-major fp16, sB[n][k] (B pre-transposed so non-trans ldmatrix
// yields b-fragments). Both use 16B-chunk XOR swizzle: chunk ^= (row&7).
__global__ __launch_bounds__(256) void k_gemm2(
    const float* __restrict__ Wl, const float* __restrict__ bl,
    const float* __restrict__ Wr, const float* __restrict__ br, int N) {
    __shared__ __align__(16) __half sA[128 * 64];
    __shared__ __align__(16) __half sB[128 * 64];
    int tid = threadIdx.x;
    int rowbase = blockIdx.x * 128;
    int colbase = blockIdx.y * 128;

    // fill A: 1024 16B chunks (8 halves each)
    for (int cid = tid; cid < 1024; cid += 256) {
        int row = cid >> 3, kc = cid & 7;
        int gr = rowbase + row;
        float4 f0, f1;
        if (gr < N) {
            f0 = *(const float4*)&g_h1[gr * 64 + kc * 8];
            f1 = *(const float4*)&g_h1[gr * 64 + kc * 8 + 4];
        } else {
            f0 = make_float4(0.f, 0.f, 0.f, 0.f); f1 = f0;
        }
        __half2 h[4];
        h[0] = __floats2half2_rn(f0.x, f0.y);
        h[1] = __floats2half2_rn(f0.z, f0.w);
        h[2] = __floats2half2_rn(f1.x, f1.y);
        h[3] = __floats2half2_rn(f1.z, f1.w);
        int dst = row * 128 + ((kc ^ (row & 7)) << 4);
        *(uint4*)((char*)sA + dst) = *(uint4*)h;
    }
    // fill B (transpose W into [n][k], fp16): 4096 k-pairs
    for (int idx = tid; idx < 4096; idx += 256) {
        int n = idx & 127, k = (idx >> 7) << 1;
        int cg = colbase + n;
        float w0, w1;
        if (cg < 256) { w0 = Wl[k * 256 + cg];       w1 = Wl[(k + 1) * 256 + cg]; }
        else          { w0 = Wr[k * 256 + cg - 256]; w1 = Wr[(k + 1) * 256 + cg - 256]; }
        int dst = n * 128 + (((k >> 3) ^ (n & 7)) << 4) + (k & 7) * 2;
        *(__half2*)((char*)sB + dst) = __floats2half2_rn(w0, w1);
    }
    __syncthreads();

    int wid = tid >> 5, lane = tid & 31;
    int warp_m = wid >> 2, warp_n = wid & 3;
    float acc[4][4][4];
#pragma unroll
    for (int mt = 0; mt < 4; mt++)
#pragma unroll
        for (int nt = 0; nt < 4; nt++)
#pragma unroll
            for (int q = 0; q < 4; q++) acc[mt][nt][q] = 0.f;

    int l7 = lane & 7;
    int akh = lane >> 4;                              // A k-half select
    unsigned aBase = smem_u32(sA) + (warp_m * 64 + (lane & 15)) * 128;
    int brow = (lane & 7) + ((lane >> 4) & 1) * 8;    // n within 16-row pair
    int bkh = (lane >> 3) & 1;                        // B k-half select
    unsigned bBase = smem_u32(sB) + (warp_n * 32 + brow) * 128;

#pragma unroll
    for (int ks = 0; ks < 4; ks++) {
        unsigned ca = (unsigned)(((ks * 2 + akh) ^ l7) << 4);
        unsigned cb = (unsigned)(((ks * 2 + bkh) ^ l7) << 4);
        unsigned a[4][4];
#pragma unroll
        for (int mt = 0; mt < 4; mt++)
            ldm4(a[mt], aBase + mt * 16 * 128 + ca);
        unsigned bb[2][4];
#pragma unroll
        for (int np = 0; np < 2; np++)
            ldm4(bb[np], bBase + np * 16 * 128 + cb);
#pragma unroll
        for (int mt = 0; mt < 4; mt++)
#pragma unroll
            for (int np = 0; np < 2; np++) {
                mma16816(acc[mt][2 * np],     a[mt], bb[np][0], bb[np][1]);
                mma16816(acc[mt][2 * np + 1], a[mt], bb[np][2], bb[np][3]);
            }
    }

    // epilogue: c0=(g,2t) c1=(g,2t+1) c2=(g+8,2t) c3=(g+8,2t+1)
    int g = lane >> 2, t4 = lane & 3;
#pragma unroll
    for (int mt = 0; mt < 4; mt++) {
        int r0 = rowbase + warp_m * 64 + mt * 16 + g;
#pragma unroll
        for (int nt = 0; nt < 4; nt++) {
            int cg = colbase + warp_n * 32 + nt * 8 + 2 * t4;
            float b0, b1;
            if (cg < 256) { b0 = bl[cg];       b1 = bl[cg + 1]; }
            else          { b0 = br[cg - 256]; b1 = br[cg - 255]; }
            const float* c = acc[mt][nt];
            if (colbase < 256) {
                if (r0 < N)
                    *(__half2*)&g_xl2h[r0 * 256 + cg] =
                        __floats2half2_rn(c[0] + b0, c[1] + b1);
                if (r0 + 8 < N)
                    *(__half2*)&g_xl2h[(r0 + 8) * 256 + cg] =
                        __floats2half2_rn(c[2] + b0, c[3] + b1);
            } else {
                int cc = cg - 256;
                if (r0 < N) {
                    float2 v; v.x = c[0] + b0; v.y = c[1] + b1;
                    *(float2*)&g_xr2[r0 * 256 + cc] = v;
                }
                if (r0 + 8 < N) {
                    float2 v; v.x = c[2] + b0; v.y = c[3] + b1;
                    *(float2*)&g_xr2[(r0 + 8) * 256 + cc] = v;
                }
            }
        }
    }
}

// ---------------- Layer 2 edge kernel (2-edge, hadd2 + dual-dot) ------------
__device__ __forceinline__ void cvt8h(const __half2* t, float* f) {
    float2 q;
    q = __half22float2(t[0]); f[0] = q.x; f[1] = q.y;
    q = __half22float2(t[1]); f[2] = q.x; f[3] = q.y;
    q = __half22float2(t[2]); f[4] = q.x; f[5] = q.y;
    q = __half22float2(t[3]); f[6] = q.x; f[7] = q.y;
}

__global__ __launch_bounds__(256, 4) void k_l2edge(
    const float* __restrict__ att, const float* __restrict__ bo,
    float* __restrict__ out, int N) {
    int warp = (blockIdx.x * blockDim.x + threadIdx.x) >> 5;
    int lane = threadIdx.x & 31;
    if (warp >= N) return;
    int i = warp;
    const int* __restrict__ csr = g_csr;
    int h8 = lane * 8;
    __half2 xrh[4];
    float av[8];
    {
        float4 r0 = *(const float4*)&g_xr2[i * 256 + h8];
        float4 r1 = *(const float4*)&g_xr2[i * 256 + h8 + 4];
        xrh[0] = __floats2half2_rn(r0.x, r0.y);
        xrh[1] = __floats2half2_rn(r0.z, r0.w);
        xrh[2] = __floats2half2_rn(r1.x, r1.y);
        xrh[3] = __floats2half2_rn(r1.z, r1.w);
        float4 a0 = __ldg((const float4*)&att[h8]);
        float4 a1 = __ldg((const float4*)&att[h8 + 4]);
        av[0] = a0.x; av[1] = a0.y; av[2] = a0.z; av[3] = a0.w;
        av[4] = a1.x; av[5] = a1.y; av[6] = a1.z; av[7] = a1.w;
    }
    float acc[8], m0, d;
    {
        uint4 raw = __ldg((const uint4*)&g_xl2h[i * 256 + h8]);
        __half2 th[4];
        const __half2* xh = (const __half2*)&raw;
#pragma unroll
        for (int q = 0; q < 4; q++) th[q] = __hadd2(xh[q], xrh[q]);
        float t[8];
        cvt8h(th, t);
        float pa = 0.f, pb = 0.f;
#pragma unroll
        for (int k = 0; k < 8; k++) {
            pa = fmaf(av[k], t[k], pa);
            pb = fmaf(av[k], fabsf(t[k]), pb);
        }
        float p = fmaf(0.6f, pa, 0.4f * pb);
        p += __shfl_xor_sync(0xFFFFFFFFu, p, 1);
        p += __shfl_xor_sync(0xFFFFFFFFu, p, 2);
        p += __shfl_xor_sync(0xFFFFFFFFu, p, 4);
        m0 = p; d = 1.f;
#pragma unroll
        for (int k = 0; k < 8; k++) acc[k] = t[k];
    }
    int beg = __ldg(&g_rowptr[i]), end = __ldg(&g_rowptr[i + 1]);
    int j = beg;
    for (; j + 1 < end; j += 2) {
        int s0 = __ldg(&csr[j]);
        int s1 = __ldg(&csr[j + 1]);
        uint4 r0 = __ldg((const uint4*)&g_xl2h[s0 * 256 + h8]);
        uint4 r1 = __ldg((const uint4*)&g_xl2h[s1 * 256 + h8]);
        __half2 t0h[4], t1h[4];
        const __half2* x0h = (const __half2*)&r0;
        const __half2* x1h = (const __half2*)&r1;
#pragma unroll
        for (int q = 0; q < 4; q++) {
            t0h[q] = __hadd2(x0h[q], xrh[q]);
            t1h[q] = __hadd2(x1h[q], xrh[q]);
        }
        float t0[8], t1[8];
        cvt8h(t0h, t0);
        cvt8h(t1h, t1);
        float pa0 = 0.f, pb0 = 0.f, pa1 = 0.f, pb1 = 0.f;
#pragma unroll
        for (int k = 0; k < 8; k++) {
            pa0 = fmaf(av[k], t0[k], pa0);
            pb0 = fmaf(av[k], fabsf(t0[k]), pb0);
            pa1 = fmaf(av[k], t1[k], pa1);
            pb1 = fmaf(av[k], fabsf(t1[k]), pb1);
        }
        float p0 = fmaf(0.6f, pa0, 0.4f * pb0);
        float p1 = fmaf(0.6f, pa1, 0.4f * pb1);
        p0 += __shfl_xor_sync(0xFFFFFFFFu, p0, 1);
        p1 += __shfl_xor_sync(0xFFFFFFFFu, p1, 1);
        p0 += __shfl_xor_sync(0xFFFFFFFFu, p0, 2);
        p1 += __shfl_xor_sync(0xFFFFFFFFu, p1, 2);
        p0 += __shfl_xor_sync(0xFFFFFFFFu, p0, 4);
        p1 += __shfl_xor_sync(0xFFFFFFFFu, p1, 4);
        float w0 = __expf(p0 - m0);
        float w1 = __expf(p1 - m0);
        d += w0 + w1;
#pragma unroll
        for (int k = 0; k < 8; k++)
            acc[k] = fmaf(w0, t0[k], fmaf(w1, t1[k], acc[k]));
    }
    if (j < end) {
        int s = __ldg(&csr[j]);
        uint4 raw = __ldg((const uint4*)&g_xl2h[s * 256 + h8]);
        __half2 th[4];
        const __half2* xh = (const __half2*)&raw;
#pragma unroll
        for (int q = 0; q < 4; q++) th[q] = __hadd2(xh[q], xrh[q]);
        float t[8];
        cvt8h(th, t);
        float pa = 0.f, pb = 0.f;
#pragma unroll
        for (int k = 0; k < 8; k++) {
            pa = fmaf(av[k], t[k], pa);
            pb = fmaf(av[k], fabsf(t[k]), pb);
        }
        float p = fmaf(0.6f, pa, 0.4f * pb);
        p += __shfl_xor_sync(0xFFFFFFFFu, p, 1);
        p += __shfl_xor_sync(0xFFFFFFFFu, p, 2);
        p += __shfl_xor_sync(0xFFFFFFFFu, p, 4);
        float w = __expf(p - m0);
        d += w;
#pragma unroll
        for (int k = 0; k < 8; k++) acc[k] = fmaf(w, t[k], acc[k]);
    }
    float inv = 1.f / d;
    float xrr[8];
    cvt8h(xrh, xrr);
    float r[8];
#pragma unroll
    for (int k = 0; k < 8; k++) r[k] = fmaf(acc[k], inv, -xrr[k]);
#pragma unroll
    for (int k = 0; k < 8; k++) r[k] += __shfl_xor_sync(0xFFFFFFFFu, r[k], 8);
#pragma unroll
    for (int k = 0; k < 8; k++) r[k] += __shfl_xor_sync(0xFFFFFFFFu, r[k], 16);
    if (lane < 8) {
        float4 b0 = __ldg((const float4*)&bo[h8]);
        float4 b1 = __ldg((const float4*)&bo[h8 + 4]);
        float4 o0, o1;
        o0.x = fmaxf(fmaf(0.25f, r[0], b0.x), 0.f);
        o0.y = fmaxf(fmaf(0.25f, r[1], b0.y), 0.f);
        o0.z = fmaxf(fmaf(0.25f, r[2], b0.z), 0.f);
        o0.w = fmaxf(fmaf(0.25f, r[3], b0.w), 0.f);
        o1.x = fmaxf(fmaf(0.25f, r[4], b1.x), 0.f);
        o1.y = fmaxf(fmaf(0.25f, r[5], b1.y), 0.f);
        o1.z = fmaxf(fmaf(0.25f, r[6], b1.z), 0.f);
        o1.w = fmaxf(fmaf(0.25f, r[7], b1.w), 0.f);
        *(float4*)&out[i * 64 + h8]     = o0;
        *(float4*)&out[i * 64 + h8 + 4] = o1;
    }
}

// ---------------- launch ----------------
extern "C" void kernel_launch(void* const* d_in, const int* in_sizes, int n_in,
                              void* d_out, int out_size) {
    const float* x   = (const float*)d_in[0];
    const void*  ei  = d_in[1];
    // d_in[2] = frame_mask (unused by the reference)
    const float* Wl1 = (const float*)d_in[3];
    const float* bl1 = (const float*)d_in[4];
    const float* Wr1 = (const float*)d_in[5];
    const float* br1 = (const float*)d_in[6];
    const float* att1 = (const float*)d_in[7];
    const float* bo1 = (const float*)d_in[8];
    const float* Wl2 = (const float*)d_in[9];
    const float* bl2 = (const float*)d_in[10];
    const float* Wr2 = (const float*)d_in[11];
    const float* br2 = (const float*)d_in[12];
    const float* att2 = (const float*)d_in[13];
    const float* bo2 = (const float*)d_in[14];

    int N = in_sizes[0] / 64;
    int E = in_sizes[1] / 2;
    if (N > NN) N = NN;
    if (E > EE) E = EE;

    // launch 0: detect + zero + gemm1 + hist + scan (grid barriers inside)
    k_fused<<<NB, NT>>>(x, Wl1, bl1, Wr1, br1, ei, N, E);
    // launch 1: CSR scatter
    k_scatter<<<(E + 255) / 256, 256>>>(ei, E);
    // launch 2: layer-1 attention
    k_l1edge<<<(N + 7) / 8, 256>>>(att1, bo1, N);
    // launch 3 (ncu slot): layer-2 transform, tensor cores
    int rb = (N + 127) / 128;
    dim3 g2(rb, 4);
    k_gemm2<<<g2, 256>>>(Wl2, bl2, Wr2, br2, N);
    // launch 4: layer-2 attention
    k_l2edge<<<(N + 7) / 8, 256>>>(att2, bo2, (float*)d_out, N);
}